// round 11
// baseline (speedup 1.0000x reference)
#include <cuda_runtime.h>
#include <cuda_fp16.h>
#include <mma.h>

using namespace nvcuda;

#define Nn 50000
#define Ee 800000
#define Hh 128
#define SK 136   // padded smem stride (halves)

// ---------------- scratch (device globals; NEVER passed as kernel args) ----
__device__ __half g_xh[(size_t)Nn * Hh];    // x rows normalized, fp16 (cosine)
__device__ __half g_ah[(size_t)Nn * Hh];    // GEMM A operand, fp16 (x or h1)
__device__ __half g_W1h[Hh * Hh];
__device__ __half g_W2h[Hh * Hh];
__device__ float g_ew[Ee];
__device__ float g_deg[Nn];
__device__ float g_dinv[Nn];
__device__ float g_xt[(size_t)Nn * Hh];     // GEMM output fp32 (gathered by aggc)
__device__ int   g_cnt[Nn];
__device__ int   g_rowptr[Nn + 1];
__device__ int   g_cur[Nn];
__device__ int   g_csr_src[Ee];
__device__ float g_csr_nrm[Ee];
__device__ int   g_not_i64;

__device__ __forceinline__ int ld_idx(const int* __restrict__ p, int i, int is64) {
    return is64 ? p[2 * i] : p[i];
}

// -------- init + dtype detection fused (grid covers Ee threads) ------------
__global__ void k_initdet(const int* __restrict__ ei) {
    int i = blockIdx.x * blockDim.x + threadIdx.x;
    if (i < Nn) { g_cnt[i] = 0; g_deg[i] = 0.f; }
    if (i == 0) g_not_i64 = 0;
    if (i < Ee && ei[2 * i + 1] != 0) atomicOr(&g_not_i64, 1);
}

// ------- normalize rows of x into fp16 (g_xh) AND raw fp16 copy (g_ah) -----
__global__ void k_xprep(const float* __restrict__ x) {
    int node = (blockIdx.x * blockDim.x + threadIdx.x) >> 5;
    int lane = threadIdx.x & 31;
    if (node >= Nn) return;
    float4 v = ((const float4*)(x + (size_t)node * Hh))[lane];
    float ss = v.x * v.x + v.y * v.y + v.z * v.z + v.w * v.w;
    #pragma unroll
    for (int o = 16; o; o >>= 1) ss += __shfl_xor_sync(0xffffffffu, ss, o);
    float inv = 1.0f / fmaxf(sqrtf(ss), 1e-8f);
    __half2 n0 = __floats2half2_rn(v.x * inv, v.y * inv);
    __half2 n1 = __floats2half2_rn(v.z * inv, v.w * inv);
    uint2 pn; pn.x = *(unsigned*)&n0; pn.y = *(unsigned*)&n1;
    ((uint2*)(g_xh + (size_t)node * Hh))[lane] = pn;
    __half2 r0 = __floats2half2_rn(v.x, v.y);
    __half2 r1 = __floats2half2_rn(v.z, v.w);
    uint2 pr; pr.x = *(unsigned*)&r0; pr.y = *(unsigned*)&r1;
    ((uint2*)(g_ah + (size_t)node * Hh))[lane] = pr;
}

// ---------------- convert W1, W2 to fp16 ----------------
__global__ void k_w2h(const float* __restrict__ W1, const float* __restrict__ W2) {
    int i = blockIdx.x * blockDim.x + threadIdx.x;
    if (i < Hh * Hh) g_W1h[i] = __float2half_rn(W1[i]);
    else if (i < 2 * Hh * Hh) g_W2h[i - Hh * Hh] = __float2half_rn(W2[i - Hh * Hh]);
}

// ------- edge weights + degree + histogram: 16 lanes per edge --------------
__global__ void k_edge(const int* __restrict__ ei,
                       const int* __restrict__ sat) {
    int gt = blockIdx.x * blockDim.x + threadIdx.x;
    int e = gt >> 4;                 // 2 edges per warp
    int sub = threadIdx.x & 15;
    if (e >= Ee) return;
    int is64 = (g_not_i64 == 0);
    unsigned s = (unsigned)ld_idx(ei, e, is64);
    unsigned d = (unsigned)ld_idx(ei, Ee + e, is64);
    if (s >= Nn || d >= Nn) return;   // never fault
    uint4 pa = ((const uint4*)(g_xh + (size_t)s * Hh))[sub];   // 8 halves
    uint4 pb = ((const uint4*)(g_xh + (size_t)d * Hh))[sub];
    float2 a0 = __half22float2(*(__half2*)&pa.x);
    float2 a1 = __half22float2(*(__half2*)&pa.y);
    float2 a2 = __half22float2(*(__half2*)&pa.z);
    float2 a3 = __half22float2(*(__half2*)&pa.w);
    float2 b0 = __half22float2(*(__half2*)&pb.x);
    float2 b1 = __half22float2(*(__half2*)&pb.y);
    float2 b2 = __half22float2(*(__half2*)&pb.z);
    float2 b3 = __half22float2(*(__half2*)&pb.w);
    float dot = a0.x * b0.x + a0.y * b0.y + a1.x * b1.x + a1.y * b1.y
              + a2.x * b2.x + a2.y * b2.y + a3.x * b3.x + a3.y * b3.y;
    #pragma unroll
    for (int o = 8; o; o >>= 1) dot += __shfl_xor_sync(0xffffffffu, dot, o);
    if (sub == 0) {
        int ss_ = ld_idx(sat, (int)s, is64);
        int sd_ = ld_idx(sat, (int)d, is64);
        float f = (ss_ != sd_) ? 0.36787944117144233f : 1.0f;  // exp(-1)
        float ew = fmaxf(dot * f, 1e-4f);
        g_ew[e] = ew;
        atomicAdd(&g_deg[d], ew);
        atomicAdd(&g_cnt[d], 1);
    }
}

// ------------- single-block prefix scan + fused dinv ------------------------
__global__ __launch_bounds__(1024) void k_scan() {
    __shared__ int sh[1024];
    const int t = threadIdx.x;
    const int CH = (Nn + 1023) / 1024;
    int beg = t * CH;
    int end = beg + CH; if (end > Nn) end = Nn;
    int sum = 0;
    for (int i = beg; i < end; i++) sum += g_cnt[i];
    sh[t] = sum;
    __syncthreads();
    for (int off = 1; off < 1024; off <<= 1) {
        int v = 0;
        if (t >= off) v = sh[t - off];
        __syncthreads();
        if (t >= off) sh[t] += v;
        __syncthreads();
    }
    int run = (t == 0) ? 0 : sh[t - 1];
    for (int i = beg; i < end; i++) {
        g_rowptr[i] = run;
        g_cur[i]    = run;
        g_dinv[i]   = rsqrtf(g_deg[i] + 1.0f);
        run += g_cnt[i];
    }
    if (t == 1023) g_rowptr[Nn] = sh[1023];
}

// ---------------- CSR fill ----------------
__global__ void k_fill(const int* __restrict__ ei) {
    int e = blockIdx.x * blockDim.x + threadIdx.x;
    if (e >= Ee) return;
    int is64 = (g_not_i64 == 0);
    unsigned s = (unsigned)ld_idx(ei, e, is64);
    unsigned d = (unsigned)ld_idx(ei, Ee + e, is64);
    if (s >= Nn || d >= Nn) return;
    float nrm = g_dinv[s] * g_ew[e] * g_dinv[d];
    int pos = atomicAdd(&g_cur[d], 1);
    g_csr_src[pos] = (int)s;
    g_csr_nrm[pos] = nrm;
}

// ------------- tensor-core GEMM: g_xt(fp32) = g_ah @ W(half) ---------------
__global__ __launch_bounds__(256) void k_gemmh(int which) {
    extern __shared__ __align__(32) __half sh[];
    __half* Ah = sh;               // [128][SK]
    __half* Wh = sh + 128 * SK;    // [128][SK]
    const __half* __restrict__ W = which ? g_W2h : g_W1h;
    int tid = threadIdx.x;
    int row0 = blockIdx.x * 128;

    for (int i = tid; i < 128 * 16; i += 256) {
        int r = i >> 4, c = i & 15;
        *((uint4*)(Wh + r * SK + c * 8)) = ((const uint4*)(W + r * 128 + c * 8))[0];
    }
    for (int i = tid; i < 128 * 16; i += 256) {
        int r = i >> 4, c = i & 15;
        int gr = row0 + r;
        uint4 v = make_uint4(0u, 0u, 0u, 0u);
        if (gr < Nn) v = ((const uint4*)(g_ah + (size_t)gr * 128 + c * 8))[0];
        *((uint4*)(Ah + r * SK + c * 8)) = v;
    }
    __syncthreads();

    int w = tid >> 5;
    wmma::fragment<wmma::accumulator, 16, 16, 16, float> acc[8];
    #pragma unroll
    for (int n = 0; n < 8; n++) wmma::fill_fragment(acc[n], 0.0f);

    #pragma unroll
    for (int k = 0; k < 8; k++) {
        wmma::fragment<wmma::matrix_a, 16, 16, 16, __half, wmma::row_major> af;
        wmma::load_matrix_sync(af, Ah + (w * 16) * SK + k * 16, SK);
        #pragma unroll
        for (int n = 0; n < 8; n++) {
            wmma::fragment<wmma::matrix_b, 16, 16, 16, __half, wmma::row_major> bf;
            wmma::load_matrix_sync(bf, Wh + (k * 16) * SK + n * 16, SK);
            wmma::mma_sync(acc[n], af, bf, acc[n]);
        }
    }

    int gr0 = row0 + w * 16;
    if (gr0 < Nn) {   // Nn multiple of 16: tile fully valid or fully out
        #pragma unroll
        for (int n = 0; n < 8; n++)
            wmma::store_matrix_sync(g_xt + (size_t)gr0 * 128 + n * 16, acc[n],
                                    128, wmma::mem_row_major);
    }
}

// ----- fused CSR aggregation (fp32, 4-way) + self-loop + bias + relu -------
// to_h1=1: write g_ah (fp16).  to_h1=0: write outext fp32 AND y head.
__global__ void k_aggc(const float* __restrict__ b, float* __restrict__ outext,
                       const float* __restrict__ Wc, const float* __restrict__ bc,
                       float* __restrict__ y, int to_h1) {
    int node = (blockIdx.x * blockDim.x + threadIdx.x) >> 5;
    int lane = threadIdx.x & 31;
    if (node >= Nn) return;
    int beg = g_rowptr[node];
    int end = g_rowptr[node + 1];

    float4 acc0 = make_float4(0.f, 0.f, 0.f, 0.f);
    float4 acc1 = make_float4(0.f, 0.f, 0.f, 0.f);

    int p = beg;
    for (; p + 3 < end; p += 4) {
        int   s0 = g_csr_src[p],     s1 = g_csr_src[p + 1];
        int   s2 = g_csr_src[p + 2], s3 = g_csr_src[p + 3];
        float n0 = g_csr_nrm[p],     n1 = g_csr_nrm[p + 1];
        float n2 = g_csr_nrm[p + 2], n3 = g_csr_nrm[p + 3];
        float4 v0 = ((const float4*)(g_xt + (size_t)s0 * Hh))[lane];
        float4 v1 = ((const float4*)(g_xt + (size_t)s1 * Hh))[lane];
        float4 v2 = ((const float4*)(g_xt + (size_t)s2 * Hh))[lane];
        float4 v3 = ((const float4*)(g_xt + (size_t)s3 * Hh))[lane];
        acc0.x += v0.x * n0; acc0.y += v0.y * n0; acc0.z += v0.z * n0; acc0.w += v0.w * n0;
        acc1.x += v1.x * n1; acc1.y += v1.y * n1; acc1.z += v1.z * n1; acc1.w += v1.w * n1;
        acc0.x += v2.x * n2; acc0.y += v2.y * n2; acc0.z += v2.z * n2; acc0.w += v2.w * n2;
        acc1.x += v3.x * n3; acc1.y += v3.y * n3; acc1.z += v3.z * n3; acc1.w += v3.w * n3;
    }
    for (; p < end; p++) {
        int   s0 = g_csr_src[p];
        float n0 = g_csr_nrm[p];
        float4 v0 = ((const float4*)(g_xt + (size_t)s0 * Hh))[lane];
        acc0.x += v0.x * n0; acc0.y += v0.y * n0; acc0.z += v0.z * n0; acc0.w += v0.w * n0;
    }

    float di = g_dinv[node];
    float d2 = di * di;
    float4 self = ((const float4*)(g_xt + (size_t)node * Hh))[lane];
    float4 bb = ((const float4*)b)[lane];
    float4 r;
    r.x = fmaxf(acc0.x + acc1.x + self.x * d2 + bb.x, 0.f);
    r.y = fmaxf(acc0.y + acc1.y + self.y * d2 + bb.y, 0.f);
    r.z = fmaxf(acc0.z + acc1.z + self.z * d2 + bb.z, 0.f);
    r.w = fmaxf(acc0.w + acc1.w + self.w * d2 + bb.w, 0.f);

    if (to_h1) {
        __half2 h0 = __floats2half2_rn(r.x, r.y);
        __half2 h1 = __floats2half2_rn(r.z, r.w);
        uint2 pk; pk.x = *(unsigned*)&h0; pk.y = *(unsigned*)&h1;
        ((uint2*)(g_ah + (size_t)node * Hh))[lane] = pk;
    } else {
        ((float4*)(outext + (size_t)node * Hh))[lane] = r;
        float4 wv = ((const float4*)Wc)[lane];
        float dot = r.x * wv.x + r.y * wv.y + r.z * wv.z + r.w * wv.w;
        #pragma unroll
        for (int o = 16; o; o >>= 1) dot += __shfl_xor_sync(0xffffffffu, dot, o);
        if (lane == 0) y[node] = dot + bc[0];
    }
}

// ---------------- launch ----------------
extern "C" void kernel_launch(void* const* d_in, const int* in_sizes, int n_in,
                              void* d_out, int out_size) {
    int ix = 0, iei = 1, isa = 2, iW1 = 3, ib1 = 4, iW2 = 5, ib2 = 6, iWc = 7, ibc = 8;
    if (n_in >= 9 && in_sizes[0] != 6400000) {
        if (in_sizes[0] == 16384 && in_sizes[1] == 16384) {
            iW1 = 0; iW2 = 1; iWc = 2; ib1 = 3; ib2 = 4; ibc = 5; iei = 6; isa = 7; ix = 8;
        } else {
            int c128a = -1, c128b = -1, c128c = -1, w16a = -1, w16b = -1;
            for (int i = 0; i < n_in; i++) {
                int s = in_sizes[i];
                if (s == 6400000) ix = i;
                else if (s == 1600000 || s == 3200000) iei = i;
                else if (s == 50000 || s == 100000) isa = i;
                else if (s == 16384) { if (w16a < 0) w16a = i; else w16b = i; }
                else if (s == 128) { if (c128a < 0) c128a = i; else if (c128b < 0) c128b = i; else c128c = i; }
                else if (s == 1) ibc = i;
            }
            iW1 = w16a; iW2 = w16b; ib1 = c128a; ib2 = c128b; iWc = c128c;
        }
    }

    const float* x  = (const float*)d_in[ix];
    const int*   ei = (const int*)d_in[iei];
    const int*   sa = (const int*)d_in[isa];
    const float* W1 = (const float*)d_in[iW1];
    const float* b1 = (const float*)d_in[ib1];
    const float* W2 = (const float*)d_in[iW2];
    const float* b2 = (const float*)d_in[ib2];
    const float* Wc = (const float*)d_in[iWc];
    const float* bc = (const float*)d_in[ibc];

    float* out  = (float*)d_out;
    float* yout = out;        // [N]
    float* hout = out + Nn;   // [N, 128]

    const int T = 256;
    const int gNwarp = (Nn + 7) / 8;
    const int gE16   = (Ee * 16 + T - 1) / T;
    const int gE     = (Ee + T - 1) / T;
    const int gGemm  = (Nn + 127) / 128;

    static int once = 0;
    if (!once) {
        cudaFuncSetAttribute(k_gemmh, cudaFuncAttributeMaxDynamicSharedMemorySize,
                             2 * 128 * SK * (int)sizeof(__half));
        once = 1;
    }
    const int SMEM = 2 * 128 * SK * (int)sizeof(__half);  // 69632 B

    k_initdet<<<gE, T>>>(ei);
    k_xprep<<<gNwarp, T>>>(x);
    k_w2h<<<(2 * Hh * Hh + T - 1) / T, T>>>(W1, W2);
    k_edge<<<gE16, T>>>(ei, sa);

    k_scan<<<1, 1024>>>();
    k_fill<<<gE, T>>>(ei);

    // layer 1
    k_gemmh<<<gGemm, T, SMEM>>>(0);
    k_aggc<<<gNwarp, T>>>(b1, nullptr, nullptr, nullptr, nullptr, 1);

    // layer 2 (+fused head)
    k_gemmh<<<gGemm, T, SMEM>>>(1);
    k_aggc<<<gNwarp, T>>>(b2, hout, Wc, bc, yout, 0);
}

// round 12
// speedup vs baseline: 1.0924x; 1.0924x over previous
#include <cuda_runtime.h>
#include <cuda_fp16.h>
#include <mma.h>

using namespace nvcuda;

#define Nn 50000
#define Ee 800000
#define Hh 128
#define SK 136   // padded smem stride (halves)

// ---------------- scratch (device globals; NEVER passed as kernel args) ----
__device__ __half g_xh[(size_t)Nn * Hh];    // x rows normalized, fp16 (cosine)
__device__ __half g_ah[(size_t)Nn * Hh];    // GEMM A operand, fp16 (x or h1)
__device__ __half g_W1h[Hh * Hh];
__device__ __half g_W2h[Hh * Hh];
__device__ float g_ew[Ee];
__device__ float g_deg[Nn];
__device__ float g_dinv[Nn];
__device__ float g_xt[(size_t)Nn * Hh];     // GEMM output fp32 (gathered by aggc)
__device__ int   g_cnt[Nn];
__device__ int   g_rowptr[Nn + 1];
__device__ int   g_cur[Nn];
__device__ float2 g_csr[Ee];                // {src_as_float_bits, nrm} interleaved
__device__ int   g_not_i64;

__device__ __forceinline__ int ld_idx(const int* __restrict__ p, int i, int is64) {
    return is64 ? p[2 * i] : p[i];
}

// ---------------- init ----------------
__global__ void k_init() {
    int i = blockIdx.x * blockDim.x + threadIdx.x;
    if (i < Nn) { g_cnt[i] = 0; g_deg[i] = 0.f; }
    if (i == 0) g_not_i64 = 0;
}

__global__ void k_detect(const int* __restrict__ ei) {
    int e = blockIdx.x * blockDim.x + threadIdx.x;
    if (e >= Ee) return;
    if (ei[2 * e + 1] != 0) atomicOr(&g_not_i64, 1);
}

// ------- normalize rows of x into fp16 (g_xh) AND raw fp16 copy (g_ah) -----
__global__ void k_xprep(const float* __restrict__ x) {
    int node = (blockIdx.x * blockDim.x + threadIdx.x) >> 5;
    int lane = threadIdx.x & 31;
    if (node >= Nn) return;
    float4 v = ((const float4*)(x + (size_t)node * Hh))[lane];
    float ss = v.x * v.x + v.y * v.y + v.z * v.z + v.w * v.w;
    #pragma unroll
    for (int o = 16; o; o >>= 1) ss += __shfl_xor_sync(0xffffffffu, ss, o);
    float inv = 1.0f / fmaxf(sqrtf(ss), 1e-8f);
    __half2 n0 = __floats2half2_rn(v.x * inv, v.y * inv);
    __half2 n1 = __floats2half2_rn(v.z * inv, v.w * inv);
    uint2 pn; pn.x = *(unsigned*)&n0; pn.y = *(unsigned*)&n1;
    ((uint2*)(g_xh + (size_t)node * Hh))[lane] = pn;
    __half2 r0 = __floats2half2_rn(v.x, v.y);
    __half2 r1 = __floats2half2_rn(v.z, v.w);
    uint2 pr; pr.x = *(unsigned*)&r0; pr.y = *(unsigned*)&r1;
    ((uint2*)(g_ah + (size_t)node * Hh))[lane] = pr;
}

// ---------------- convert W1, W2 to fp16 ----------------
__global__ void k_w2h(const float* __restrict__ W1, const float* __restrict__ W2) {
    int i = blockIdx.x * blockDim.x + threadIdx.x;
    if (i < Hh * Hh) g_W1h[i] = __float2half_rn(W1[i]);
    else if (i < 2 * Hh * Hh) g_W2h[i - Hh * Hh] = __float2half_rn(W2[i - Hh * Hh]);
}

// ------- edge weights + degree + histogram: 16 lanes per edge --------------
__global__ void k_edge(const int* __restrict__ ei,
                       const int* __restrict__ sat) {
    int gt = blockIdx.x * blockDim.x + threadIdx.x;
    int e = gt >> 4;                 // 2 edges per warp
    int sub = threadIdx.x & 15;
    if (e >= Ee) return;
    int is64 = (g_not_i64 == 0);
    unsigned s = (unsigned)ld_idx(ei, e, is64);
    unsigned d = (unsigned)ld_idx(ei, Ee + e, is64);
    if (s >= Nn || d >= Nn) return;   // never fault
    uint4 pa = ((const uint4*)(g_xh + (size_t)s * Hh))[sub];   // 8 halves
    uint4 pb = ((const uint4*)(g_xh + (size_t)d * Hh))[sub];
    float2 a0 = __half22float2(*(__half2*)&pa.x);
    float2 a1 = __half22float2(*(__half2*)&pa.y);
    float2 a2 = __half22float2(*(__half2*)&pa.z);
    float2 a3 = __half22float2(*(__half2*)&pa.w);
    float2 b0 = __half22float2(*(__half2*)&pb.x);
    float2 b1 = __half22float2(*(__half2*)&pb.y);
    float2 b2 = __half22float2(*(__half2*)&pb.z);
    float2 b3 = __half22float2(*(__half2*)&pb.w);
    float dot = a0.x * b0.x + a0.y * b0.y + a1.x * b1.x + a1.y * b1.y
              + a2.x * b2.x + a2.y * b2.y + a3.x * b3.x + a3.y * b3.y;
    #pragma unroll
    for (int o = 8; o; o >>= 1) dot += __shfl_xor_sync(0xffffffffu, dot, o);
    if (sub == 0) {
        int ss_ = ld_idx(sat, (int)s, is64);
        int sd_ = ld_idx(sat, (int)d, is64);
        float f = (ss_ != sd_) ? 0.36787944117144233f : 1.0f;  // exp(-1)
        float ew = fmaxf(dot * f, 1e-4f);
        g_ew[e] = ew;
        atomicAdd(&g_deg[d], ew);
        atomicAdd(&g_cnt[d], 1);
    }
}

// ---------------- dinv = (deg + 1)^-0.5 (separate, parallel) ---------------
__global__ void k_dinv() {
    int i = blockIdx.x * blockDim.x + threadIdx.x;
    if (i < Nn) g_dinv[i] = rsqrtf(g_deg[i] + 1.0f);
}

// ------------- single-block prefix scan (counts only) ----------------------
__global__ __launch_bounds__(1024) void k_scan() {
    __shared__ int sh[1024];
    const int t = threadIdx.x;
    const int CH = (Nn + 1023) / 1024;
    int beg = t * CH;
    int end = beg + CH; if (end > Nn) end = Nn;
    int sum = 0;
    for (int i = beg; i < end; i++) sum += g_cnt[i];
    sh[t] = sum;
    __syncthreads();
    for (int off = 1; off < 1024; off <<= 1) {
        int v = 0;
        if (t >= off) v = sh[t - off];
        __syncthreads();
        if (t >= off) sh[t] += v;
        __syncthreads();
    }
    int run = (t == 0) ? 0 : sh[t - 1];
    for (int i = beg; i < end; i++) {
        g_rowptr[i] = run;
        g_cur[i]    = run;
        run += g_cnt[i];
    }
    if (t == 1023) g_rowptr[Nn] = sh[1023];
}

// ---------------- CSR fill (interleaved payload) ----------------------------
__global__ void k_fill(const int* __restrict__ ei) {
    int e = blockIdx.x * blockDim.x + threadIdx.x;
    if (e >= Ee) return;
    int is64 = (g_not_i64 == 0);
    unsigned s = (unsigned)ld_idx(ei, e, is64);
    unsigned d = (unsigned)ld_idx(ei, Ee + e, is64);
    if (s >= Nn || d >= Nn) return;
    float nrm = g_dinv[s] * g_ew[e] * g_dinv[d];
    int pos = atomicAdd(&g_cur[d], 1);
    g_csr[pos] = make_float2(__int_as_float((int)s), nrm);
}

// ------------- tensor-core GEMM: g_xt(fp32) = g_ah @ W(half) ---------------
__global__ __launch_bounds__(256) void k_gemmh(int which) {
    extern __shared__ __align__(32) __half sh[];
    __half* Ah = sh;               // [128][SK]
    __half* Wh = sh + 128 * SK;    // [128][SK]
    const __half* __restrict__ W = which ? g_W2h : g_W1h;
    int tid = threadIdx.x;
    int row0 = blockIdx.x * 128;

    for (int i = tid; i < 128 * 16; i += 256) {
        int r = i >> 4, c = i & 15;
        *((uint4*)(Wh + r * SK + c * 8)) = ((const uint4*)(W + r * 128 + c * 8))[0];
    }
    for (int i = tid; i < 128 * 16; i += 256) {
        int r = i >> 4, c = i & 15;
        int gr = row0 + r;
        uint4 v = make_uint4(0u, 0u, 0u, 0u);
        if (gr < Nn) v = ((const uint4*)(g_ah + (size_t)gr * 128 + c * 8))[0];
        *((uint4*)(Ah + r * SK + c * 8)) = v;
    }
    __syncthreads();

    int w = tid >> 5;
    wmma::fragment<wmma::accumulator, 16, 16, 16, float> acc[8];
    #pragma unroll
    for (int n = 0; n < 8; n++) wmma::fill_fragment(acc[n], 0.0f);

    #pragma unroll
    for (int k = 0; k < 8; k++) {
        wmma::fragment<wmma::matrix_a, 16, 16, 16, __half, wmma::row_major> af;
        wmma::load_matrix_sync(af, Ah + (w * 16) * SK + k * 16, SK);
        #pragma unroll
        for (int n = 0; n < 8; n++) {
            wmma::fragment<wmma::matrix_b, 16, 16, 16, __half, wmma::row_major> bf;
            wmma::load_matrix_sync(bf, Wh + (k * 16) * SK + n * 16, SK);
            wmma::mma_sync(acc[n], af, bf, acc[n]);
        }
    }

    int gr0 = row0 + w * 16;
    if (gr0 < Nn) {   // Nn multiple of 16: tile fully valid or fully out
        #pragma unroll
        for (int n = 0; n < 8; n++)
            wmma::store_matrix_sync(g_xt + (size_t)gr0 * 128 + n * 16, acc[n],
                                    128, wmma::mem_row_major);
    }
}

// ----- fused CSR aggregation (fp32, 2-way) + self-loop + bias + relu -------
// to_h1=1: write g_ah (fp16).  to_h1=0: write outext fp32 AND y head.
__global__ void k_aggc(const float* __restrict__ b, float* __restrict__ outext,
                       const float* __restrict__ Wc, const float* __restrict__ bc,
                       float* __restrict__ y, int to_h1) {
    int node = (blockIdx.x * blockDim.x + threadIdx.x) >> 5;
    int lane = threadIdx.x & 31;
    if (node >= Nn) return;
    int beg = g_rowptr[node];
    int end = g_rowptr[node + 1];

    float4 acc0 = make_float4(0.f, 0.f, 0.f, 0.f);
    float4 acc1 = make_float4(0.f, 0.f, 0.f, 0.f);

    int p = beg;
    for (; p + 1 < end; p += 2) {
        float2 c0 = g_csr[p];
        float2 c1 = g_csr[p + 1];
        int   s0 = __float_as_int(c0.x);   float n0 = c0.y;
        int   s1 = __float_as_int(c1.x);   float n1 = c1.y;
        float4 v0 = ((const float4*)(g_xt + (size_t)s0 * Hh))[lane];
        float4 v1 = ((const float4*)(g_xt + (size_t)s1 * Hh))[lane];
        acc0.x += v0.x * n0; acc0.y += v0.y * n0; acc0.z += v0.z * n0; acc0.w += v0.w * n0;
        acc1.x += v1.x * n1; acc1.y += v1.y * n1; acc1.z += v1.z * n1; acc1.w += v1.w * n1;
    }
    if (p < end) {
        float2 c0 = g_csr[p];
        int   s0 = __float_as_int(c0.x);   float n0 = c0.y;
        float4 v0 = ((const float4*)(g_xt + (size_t)s0 * Hh))[lane];
        acc0.x += v0.x * n0; acc0.y += v0.y * n0; acc0.z += v0.z * n0; acc0.w += v0.w * n0;
    }

    float di = g_dinv[node];
    float d2 = di * di;
    float4 self = ((const float4*)(g_xt + (size_t)node * Hh))[lane];
    float4 bb = ((const float4*)b)[lane];
    float4 r;
    r.x = fmaxf(acc0.x + acc1.x + self.x * d2 + bb.x, 0.f);
    r.y = fmaxf(acc0.y + acc1.y + self.y * d2 + bb.y, 0.f);
    r.z = fmaxf(acc0.z + acc1.z + self.z * d2 + bb.z, 0.f);
    r.w = fmaxf(acc0.w + acc1.w + self.w * d2 + bb.w, 0.f);

    if (to_h1) {
        __half2 h0 = __floats2half2_rn(r.x, r.y);
        __half2 h1 = __floats2half2_rn(r.z, r.w);
        uint2 pk; pk.x = *(unsigned*)&h0; pk.y = *(unsigned*)&h1;
        ((uint2*)(g_ah + (size_t)node * Hh))[lane] = pk;
    } else {
        ((float4*)(outext + (size_t)node * Hh))[lane] = r;
        float4 wv = ((const float4*)Wc)[lane];
        float dot = r.x * wv.x + r.y * wv.y + r.z * wv.z + r.w * wv.w;
        #pragma unroll
        for (int o = 16; o; o >>= 1) dot += __shfl_xor_sync(0xffffffffu, dot, o);
        if (lane == 0) y[node] = dot + bc[0];
    }
}

// ---------------- launch ----------------
extern "C" void kernel_launch(void* const* d_in, const int* in_sizes, int n_in,
                              void* d_out, int out_size) {
    int ix = 0, iei = 1, isa = 2, iW1 = 3, ib1 = 4, iW2 = 5, ib2 = 6, iWc = 7, ibc = 8;
    if (n_in >= 9 && in_sizes[0] != 6400000) {
        if (in_sizes[0] == 16384 && in_sizes[1] == 16384) {
            iW1 = 0; iW2 = 1; iWc = 2; ib1 = 3; ib2 = 4; ibc = 5; iei = 6; isa = 7; ix = 8;
        } else {
            int c128a = -1, c128b = -1, c128c = -1, w16a = -1, w16b = -1;
            for (int i = 0; i < n_in; i++) {
                int s = in_sizes[i];
                if (s == 6400000) ix = i;
                else if (s == 1600000 || s == 3200000) iei = i;
                else if (s == 50000 || s == 100000) isa = i;
                else if (s == 16384) { if (w16a < 0) w16a = i; else w16b = i; }
                else if (s == 128) { if (c128a < 0) c128a = i; else if (c128b < 0) c128b = i; else c128c = i; }
                else if (s == 1) ibc = i;
            }
            iW1 = w16a; iW2 = w16b; ib1 = c128a; ib2 = c128b; iWc = c128c;
        }
    }

    const float* x  = (const float*)d_in[ix];
    const int*   ei = (const int*)d_in[iei];
    const int*   sa = (const int*)d_in[isa];
    const float* W1 = (const float*)d_in[iW1];
    const float* b1 = (const float*)d_in[ib1];
    const float* W2 = (const float*)d_in[iW2];
    const float* b2 = (const float*)d_in[ib2];
    const float* Wc = (const float*)d_in[iWc];
    const float* bc = (const float*)d_in[ibc];

    float* out  = (float*)d_out;
    float* yout = out;        // [N]
    float* hout = out + Nn;   // [N, 128]

    const int T = 256;
    const int gN     = (Nn + T - 1) / T;
    const int gNwarp = (Nn + 7) / 8;
    const int gE16   = (Ee * 16 + T - 1) / T;
    const int gE     = (Ee + T - 1) / T;
    const int gGemm  = (Nn + 127) / 128;

    static int once = 0;
    if (!once) {
        cudaFuncSetAttribute(k_gemmh, cudaFuncAttributeMaxDynamicSharedMemorySize,
                             2 * 128 * SK * (int)sizeof(__half));
        once = 1;
    }
    const int SMEM = 2 * 128 * SK * (int)sizeof(__half);  // 69632 B

    k_init<<<gN, T>>>();
    k_detect<<<gE, T>>>(ei);

    k_xprep<<<gNwarp, T>>>(x);
    k_w2h<<<(2 * Hh * Hh + T - 1) / T, T>>>(W1, W2);
    k_edge<<<gE16, T>>>(ei, sa);

    k_scan<<<1, 1024>>>();
    k_dinv<<<gN, T>>>();
    k_fill<<<gE, T>>>(ei);

    // layer 1
    k_gemmh<<<gGemm, T, SMEM>>>(0);
    k_aggc<<<gNwarp, T>>>(b1, nullptr, nullptr, nullptr, nullptr, 1);

    // layer 2 (+fused head)
    k_gemmh<<<gGemm, T, SMEM>>>(1);
    k_aggc<<<gNwarp, T>>>(b2, hout, Wc, bc, yout, 0);
}

// round 13
// speedup vs baseline: 1.1998x; 1.0983x over previous
#include <cuda_runtime.h>
#include <cuda_fp16.h>
#include <mma.h>

using namespace nvcuda;

#define Nn 50000
#define Ee 800000
#define Hh 128
#define SK 136   // padded smem stride (halves)

// ---------------- scratch (device globals; NEVER passed as kernel args) ----
__device__ __half g_xh[(size_t)Nn * Hh];    // x rows normalized, fp16 (cosine)
__device__ __half g_ah[(size_t)Nn * Hh];    // GEMM A operand, fp16 (x or h1)
__device__ __half g_W1h[Hh * Hh];
__device__ __half g_W2h[Hh * Hh];
__device__ float g_ew[Ee];
__device__ float g_deg[Nn];
__device__ float g_dinv[Nn];
__device__ float g_xt[(size_t)Nn * Hh];     // GEMM output fp32 (gathered by aggc)
__device__ int   g_cnt[Nn];
__device__ int   g_rowptr[Nn + 1];
__device__ int   g_cur[Nn];
__device__ int   g_csr_src[Ee];
__device__ float g_csr_nrm[Ee];
__device__ int   g_not_i64;

__device__ __forceinline__ int ld_idx(const int* __restrict__ p, int i, int is64) {
    return is64 ? p[2 * i] : p[i];
}

// ---------------- init ----------------
__global__ void k_init() {
    int i = blockIdx.x * blockDim.x + threadIdx.x;
    if (i < Nn) { g_cnt[i] = 0; g_deg[i] = 0.f; }
    if (i == 0) g_not_i64 = 0;
}

// ---- dtype detection: sample 2048 odd words (single block, ~2us) ----------
// int64 (little-endian, indices < 2^31): odd words all zero.
// int32: odd words are random indices; P(2048 consecutive all zero) ~ 0.
__global__ void k_detect(const int* __restrict__ ei) {
    int nz = 0;
    for (int i = threadIdx.x; i < 2048; i += blockDim.x)
        nz |= (ei[2 * i + 1] != 0);
    // warp-or then block-or via atomic (tiny)
    #pragma unroll
    for (int o = 16; o; o >>= 1) nz |= __shfl_xor_sync(0xffffffffu, nz, o);
    if ((threadIdx.x & 31) == 0 && nz) atomicOr(&g_not_i64, 1);
}

// ------- normalize rows of x into fp16 (g_xh) AND raw fp16 copy (g_ah) -----
__global__ void k_xprep(const float* __restrict__ x) {
    int node = (blockIdx.x * blockDim.x + threadIdx.x) >> 5;
    int lane = threadIdx.x & 31;
    if (node >= Nn) return;
    float4 v = ((const float4*)(x + (size_t)node * Hh))[lane];
    float ss = v.x * v.x + v.y * v.y + v.z * v.z + v.w * v.w;
    #pragma unroll
    for (int o = 16; o; o >>= 1) ss += __shfl_xor_sync(0xffffffffu, ss, o);
    float inv = 1.0f / fmaxf(sqrtf(ss), 1e-8f);
    __half2 n0 = __floats2half2_rn(v.x * inv, v.y * inv);
    __half2 n1 = __floats2half2_rn(v.z * inv, v.w * inv);
    uint2 pn; pn.x = *(unsigned*)&n0; pn.y = *(unsigned*)&n1;
    ((uint2*)(g_xh + (size_t)node * Hh))[lane] = pn;
    __half2 r0 = __floats2half2_rn(v.x, v.y);
    __half2 r1 = __floats2half2_rn(v.z, v.w);
    uint2 pr; pr.x = *(unsigned*)&r0; pr.y = *(unsigned*)&r1;
    ((uint2*)(g_ah + (size_t)node * Hh))[lane] = pr;
}

// ---------------- convert W1, W2 to fp16 ----------------
__global__ void k_w2h(const float* __restrict__ W1, const float* __restrict__ W2) {
    int i = blockIdx.x * blockDim.x + threadIdx.x;
    if (i < Hh * Hh) g_W1h[i] = __float2half_rn(W1[i]);
    else if (i < 2 * Hh * Hh) g_W2h[i - Hh * Hh] = __float2half_rn(W2[i - Hh * Hh]);
}

// ------- edge weights + degree + histogram: 16 lanes per edge --------------
__global__ void k_edge(const int* __restrict__ ei,
                       const int* __restrict__ sat) {
    int gt = blockIdx.x * blockDim.x + threadIdx.x;
    int e = gt >> 4;                 // 2 edges per warp
    int sub = threadIdx.x & 15;
    if (e >= Ee) return;
    int is64 = (g_not_i64 == 0);
    unsigned s = (unsigned)ld_idx(ei, e, is64);
    unsigned d = (unsigned)ld_idx(ei, Ee + e, is64);
    if (s >= Nn || d >= Nn) return;   // never fault
    uint4 pa = ((const uint4*)(g_xh + (size_t)s * Hh))[sub];   // 8 halves
    uint4 pb = ((const uint4*)(g_xh + (size_t)d * Hh))[sub];
    float2 a0 = __half22float2(*(__half2*)&pa.x);
    float2 a1 = __half22float2(*(__half2*)&pa.y);
    float2 a2 = __half22float2(*(__half2*)&pa.z);
    float2 a3 = __half22float2(*(__half2*)&pa.w);
    float2 b0 = __half22float2(*(__half2*)&pb.x);
    float2 b1 = __half22float2(*(__half2*)&pb.y);
    float2 b2 = __half22float2(*(__half2*)&pb.z);
    float2 b3 = __half22float2(*(__half2*)&pb.w);
    float dot = a0.x * b0.x + a0.y * b0.y + a1.x * b1.x + a1.y * b1.y
              + a2.x * b2.x + a2.y * b2.y + a3.x * b3.x + a3.y * b3.y;
    #pragma unroll
    for (int o = 8; o; o >>= 1) dot += __shfl_xor_sync(0xffffffffu, dot, o);
    if (sub == 0) {
        int ss_ = ld_idx(sat, (int)s, is64);
        int sd_ = ld_idx(sat, (int)d, is64);
        float f = (ss_ != sd_) ? 0.36787944117144233f : 1.0f;  // exp(-1)
        float ew = fmaxf(dot * f, 1e-4f);
        g_ew[e] = ew;
        atomicAdd(&g_deg[d], ew);
        atomicAdd(&g_cnt[d], 1);
    }
}

// ---------------- dinv = (deg + 1)^-0.5 ----------------
__global__ void k_dinv() {
    int i = blockIdx.x * blockDim.x + threadIdx.x;
    if (i < Nn) g_dinv[i] = rsqrtf(g_deg[i] + 1.0f);
}

// ------------- single-block prefix scan (counts only) ----------------------
__global__ __launch_bounds__(1024) void k_scan() {
    __shared__ int sh[1024];
    const int t = threadIdx.x;
    const int CH = (Nn + 1023) / 1024;
    int beg = t * CH;
    int end = beg + CH; if (end > Nn) end = Nn;
    int sum = 0;
    for (int i = beg; i < end; i++) sum += g_cnt[i];
    sh[t] = sum;
    __syncthreads();
    for (int off = 1; off < 1024; off <<= 1) {
        int v = 0;
        if (t >= off) v = sh[t - off];
        __syncthreads();
        if (t >= off) sh[t] += v;
        __syncthreads();
    }
    int run = (t == 0) ? 0 : sh[t - 1];
    for (int i = beg; i < end; i++) {
        g_rowptr[i] = run;
        g_cur[i]    = run;
        run += g_cnt[i];
    }
    if (t == 1023) g_rowptr[Nn] = sh[1023];
}

// ---------------- CSR fill ----------------
__global__ void k_fill(const int* __restrict__ ei) {
    int e = blockIdx.x * blockDim.x + threadIdx.x;
    if (e >= Ee) return;
    int is64 = (g_not_i64 == 0);
    unsigned s = (unsigned)ld_idx(ei, e, is64);
    unsigned d = (unsigned)ld_idx(ei, Ee + e, is64);
    if (s >= Nn || d >= Nn) return;
    float nrm = g_dinv[s] * g_ew[e] * g_dinv[d];
    int pos = atomicAdd(&g_cur[d], 1);
    g_csr_src[pos] = (int)s;
    g_csr_nrm[pos] = nrm;
}

// ------------- tensor-core GEMM: g_xt(fp32) = g_ah @ W(half) ---------------
__global__ __launch_bounds__(256) void k_gemmh(int which) {
    extern __shared__ __align__(32) __half sh[];
    __half* Ah = sh;               // [128][SK]
    __half* Wh = sh + 128 * SK;    // [128][SK]
    const __half* __restrict__ W = which ? g_W2h : g_W1h;
    int tid = threadIdx.x;
    int row0 = blockIdx.x * 128;

    for (int i = tid; i < 128 * 16; i += 256) {
        int r = i >> 4, c = i & 15;
        *((uint4*)(Wh + r * SK + c * 8)) = ((const uint4*)(W + r * 128 + c * 8))[0];
    }
    for (int i = tid; i < 128 * 16; i += 256) {
        int r = i >> 4, c = i & 15;
        int gr = row0 + r;
        uint4 v = make_uint4(0u, 0u, 0u, 0u);
        if (gr < Nn) v = ((const uint4*)(g_ah + (size_t)gr * 128 + c * 8))[0];
        *((uint4*)(Ah + r * SK + c * 8)) = v;
    }
    __syncthreads();

    int w = tid >> 5;
    wmma::fragment<wmma::accumulator, 16, 16, 16, float> acc[8];
    #pragma unroll
    for (int n = 0; n < 8; n++) wmma::fill_fragment(acc[n], 0.0f);

    #pragma unroll
    for (int k = 0; k < 8; k++) {
        wmma::fragment<wmma::matrix_a, 16, 16, 16, __half, wmma::row_major> af;
        wmma::load_matrix_sync(af, Ah + (w * 16) * SK + k * 16, SK);
        #pragma unroll
        for (int n = 0; n < 8; n++) {
            wmma::fragment<wmma::matrix_b, 16, 16, 16, __half, wmma::row_major> bf;
            wmma::load_matrix_sync(bf, Wh + (k * 16) * SK + n * 16, SK);
            wmma::mma_sync(acc[n], af, bf, acc[n]);
        }
    }

    int gr0 = row0 + w * 16;
    if (gr0 < Nn) {   // Nn multiple of 16: tile fully valid or fully out
        #pragma unroll
        for (int n = 0; n < 8; n++)
            wmma::store_matrix_sync(g_xt + (size_t)gr0 * 128 + n * 16, acc[n],
                                    128, wmma::mem_row_major);
    }
}

// ----- fused CSR aggregation (fp32, 2-way) + self-loop + bias + relu -------
// to_h1=1: write g_ah (fp16).  to_h1=0: write outext fp32 AND y head.
__global__ void k_aggc(const float* __restrict__ b, float* __restrict__ outext,
                       const float* __restrict__ Wc, const float* __restrict__ bc,
                       float* __restrict__ y, int to_h1) {
    int node = (blockIdx.x * blockDim.x + threadIdx.x) >> 5;
    int lane = threadIdx.x & 31;
    if (node >= Nn) return;
    int beg = g_rowptr[node];
    int end = g_rowptr[node + 1];

    float4 acc0 = make_float4(0.f, 0.f, 0.f, 0.f);
    float4 acc1 = make_float4(0.f, 0.f, 0.f, 0.f);

    int p = beg;
    for (; p + 1 < end; p += 2) {
        int   s0 = g_csr_src[p],     s1 = g_csr_src[p + 1];
        float n0 = g_csr_nrm[p],     n1 = g_csr_nrm[p + 1];
        float4 v0 = ((const float4*)(g_xt + (size_t)s0 * Hh))[lane];
        float4 v1 = ((const float4*)(g_xt + (size_t)s1 * Hh))[lane];
        acc0.x += v0.x * n0; acc0.y += v0.y * n0; acc0.z += v0.z * n0; acc0.w += v0.w * n0;
        acc1.x += v1.x * n1; acc1.y += v1.y * n1; acc1.z += v1.z * n1; acc1.w += v1.w * n1;
    }
    if (p < end) {
        int   s0 = g_csr_src[p];
        float n0 = g_csr_nrm[p];
        float4 v0 = ((const float4*)(g_xt + (size_t)s0 * Hh))[lane];
        acc0.x += v0.x * n0; acc0.y += v0.y * n0; acc0.z += v0.z * n0; acc0.w += v0.w * n0;
    }

    float di = g_dinv[node];
    float d2 = di * di;
    float4 self = ((const float4*)(g_xt + (size_t)node * Hh))[lane];
    float4 bb = ((const float4*)b)[lane];
    float4 r;
    r.x = fmaxf(acc0.x + acc1.x + self.x * d2 + bb.x, 0.f);
    r.y = fmaxf(acc0.y + acc1.y + self.y * d2 + bb.y, 0.f);
    r.z = fmaxf(acc0.z + acc1.z + self.z * d2 + bb.z, 0.f);
    r.w = fmaxf(acc0.w + acc1.w + self.w * d2 + bb.w, 0.f);

    if (to_h1) {
        __half2 h0 = __floats2half2_rn(r.x, r.y);
        __half2 h1 = __floats2half2_rn(r.z, r.w);
        uint2 pk; pk.x = *(unsigned*)&h0; pk.y = *(unsigned*)&h1;
        ((uint2*)(g_ah + (size_t)node * Hh))[lane] = pk;
    } else {
        ((float4*)(outext + (size_t)node * Hh))[lane] = r;
        float4 wv = ((const float4*)Wc)[lane];
        float dot = r.x * wv.x + r.y * wv.y + r.z * wv.z + r.w * wv.w;
        #pragma unroll
        for (int o = 16; o; o >>= 1) dot += __shfl_xor_sync(0xffffffffu, dot, o);
        if (lane == 0) y[node] = dot + bc[0];
    }
}

// ---------------- launch ----------------
extern "C" void kernel_launch(void* const* d_in, const int* in_sizes, int n_in,
                              void* d_out, int out_size) {
    int ix = 0, iei = 1, isa = 2, iW1 = 3, ib1 = 4, iW2 = 5, ib2 = 6, iWc = 7, ibc = 8;
    if (n_in >= 9 && in_sizes[0] != 6400000) {
        if (in_sizes[0] == 16384 && in_sizes[1] == 16384) {
            iW1 = 0; iW2 = 1; iWc = 2; ib1 = 3; ib2 = 4; ibc = 5; iei = 6; isa = 7; ix = 8;
        } else {
            int c128a = -1, c128b = -1, c128c = -1, w16a = -1, w16b = -1;
            for (int i = 0; i < n_in; i++) {
                int s = in_sizes[i];
                if (s == 6400000) ix = i;
                else if (s == 1600000 || s == 3200000) iei = i;
                else if (s == 50000 || s == 100000) isa = i;
                else if (s == 16384) { if (w16a < 0) w16a = i; else w16b = i; }
                else if (s == 128) { if (c128a < 0) c128a = i; else if (c128b < 0) c128b = i; else c128c = i; }
                else if (s == 1) ibc = i;
            }
            iW1 = w16a; iW2 = w16b; ib1 = c128a; ib2 = c128b; iWc = c128c;
        }
    }

    const float* x  = (const float*)d_in[ix];
    const int*   ei = (const int*)d_in[iei];
    const int*   sa = (const int*)d_in[isa];
    const float* W1 = (const float*)d_in[iW1];
    const float* b1 = (const float*)d_in[ib1];
    const float* W2 = (const float*)d_in[iW2];
    const float* b2 = (const float*)d_in[ib2];
    const float* Wc = (const float*)d_in[iWc];
    const float* bc = (const float*)d_in[ibc];

    float* out  = (float*)d_out;
    float* yout = out;        // [N]
    float* hout = out + Nn;   // [N, 128]

    const int T = 256;
    const int gN     = (Nn + T - 1) / T;
    const int gNwarp = (Nn + 7) / 8;
    const int gE16   = (Ee * 16 + T - 1) / T;
    const int gE     = (Ee + T - 1) / T;
    const int gGemm  = (Nn + 127) / 128;

    static int once = 0;
    if (!once) {
        cudaFuncSetAttribute(k_gemmh, cudaFuncAttributeMaxDynamicSharedMemorySize,
                             2 * 128 * SK * (int)sizeof(__half));
        once = 1;
    }
    const int SMEM = 2 * 128 * SK * (int)sizeof(__half);  // 69632 B

    k_init<<<gN, T>>>();
    k_detect<<<1, 256>>>(ei);

    k_xprep<<<gNwarp, T>>>(x);
    k_w2h<<<(2 * Hh * Hh + T - 1) / T, T>>>(W1, W2);
    k_edge<<<gE16, T>>>(ei, sa);

    k_scan<<<1, 1024>>>();
    k_dinv<<<gN, T>>>();
    k_fill<<<gE, T>>>(ei);

    // layer 1
    k_gemmh<<<gGemm, T, SMEM>>>(0);
    k_aggc<<<gNwarp, T>>>(b1, nullptr, nullptr, nullptr, nullptr, 1);

    // layer 2 (+fused head)
    k_gemmh<<<gGemm, T, SMEM>>>(1);
    k_aggc<<<gNwarp, T>>>(b2, hout, Wc, bc, yout, 0);
}

// round 14
// speedup vs baseline: 1.2000x; 1.0001x over previous
#include <cuda_runtime.h>
#include <cuda_fp16.h>
#include <mma.h>

using namespace nvcuda;

#define Nn 50000
#define Ee 800000
#define Hh 128
#define SK 136   // padded smem stride (halves)

// ---------------- scratch (device globals; NEVER passed as kernel args) ----
__device__ __half g_xh[(size_t)Nn * Hh];    // x rows normalized, fp16 (cosine)
__device__ __half g_ah[(size_t)Nn * Hh];    // GEMM A operand, fp16 (x or h1)
__device__ __half g_W1h[Hh * Hh];
__device__ __half g_W2h[Hh * Hh];
__device__ float g_ew[Ee];
__device__ float g_deg[Nn];
__device__ float g_dinv[Nn];
__device__ float g_xt[(size_t)Nn * Hh];     // GEMM output fp32 (gathered by aggc)
__device__ int   g_cnt[Nn];
__device__ int   g_rowptr[Nn + 1];
__device__ int   g_cur[Nn];
__device__ int   g_csr_src[Ee];
__device__ float g_csr_nrm[Ee];
__device__ int   g_not_i64;

__device__ __forceinline__ int ld_idx(const int* __restrict__ p, int i, int is64) {
    return is64 ? p[2 * i] : p[i];
}

// ---------------- init ----------------
__global__ void k_init() {
    int i = blockIdx.x * blockDim.x + threadIdx.x;
    if (i < Nn) { g_cnt[i] = 0; g_deg[i] = 0.f; }
    if (i == 0) g_not_i64 = 0;
}

// ---- dtype detection: sample 2048 odd words (single block, ~2us) ----------
__global__ void k_detect(const int* __restrict__ ei) {
    int nz = 0;
    for (int i = threadIdx.x; i < 2048; i += blockDim.x)
        nz |= (ei[2 * i + 1] != 0);
    #pragma unroll
    for (int o = 16; o; o >>= 1) nz |= __shfl_xor_sync(0xffffffffu, nz, o);
    if ((threadIdx.x & 31) == 0 && nz) atomicOr(&g_not_i64, 1);
}

// ------- normalize rows of x into fp16 (g_xh) AND raw fp16 copy (g_ah) -----
__global__ void k_xprep(const float* __restrict__ x) {
    int node = (blockIdx.x * blockDim.x + threadIdx.x) >> 5;
    int lane = threadIdx.x & 31;
    if (node >= Nn) return;
    float4 v = ((const float4*)(x + (size_t)node * Hh))[lane];
    float ss = v.x * v.x + v.y * v.y + v.z * v.z + v.w * v.w;
    #pragma unroll
    for (int o = 16; o; o >>= 1) ss += __shfl_xor_sync(0xffffffffu, ss, o);
    float inv = 1.0f / fmaxf(sqrtf(ss), 1e-8f);
    __half2 n0 = __floats2half2_rn(v.x * inv, v.y * inv);
    __half2 n1 = __floats2half2_rn(v.z * inv, v.w * inv);
    uint2 pn; pn.x = *(unsigned*)&n0; pn.y = *(unsigned*)&n1;
    ((uint2*)(g_xh + (size_t)node * Hh))[lane] = pn;
    __half2 r0 = __floats2half2_rn(v.x, v.y);
    __half2 r1 = __floats2half2_rn(v.z, v.w);
    uint2 pr; pr.x = *(unsigned*)&r0; pr.y = *(unsigned*)&r1;
    ((uint2*)(g_ah + (size_t)node * Hh))[lane] = pr;
}

// ---------------- convert W1, W2 to fp16 ----------------
__global__ void k_w2h(const float* __restrict__ W1, const float* __restrict__ W2) {
    int i = blockIdx.x * blockDim.x + threadIdx.x;
    if (i < Hh * Hh) g_W1h[i] = __float2half_rn(W1[i]);
    else if (i < 2 * Hh * Hh) g_W2h[i - Hh * Hh] = __float2half_rn(W2[i - Hh * Hh]);
}

// ------- edge weights + degree + histogram: 16 lanes per edge --------------
__global__ void k_edge(const int* __restrict__ ei,
                       const int* __restrict__ sat) {
    int gt = blockIdx.x * blockDim.x + threadIdx.x;
    int e = gt >> 4;                 // 2 edges per warp
    int sub = threadIdx.x & 15;
    if (e >= Ee) return;
    int is64 = (g_not_i64 == 0);
    unsigned s = (unsigned)ld_idx(ei, e, is64);
    unsigned d = (unsigned)ld_idx(ei, Ee + e, is64);
    if (s >= Nn || d >= Nn) return;   // never fault
    uint4 pa = ((const uint4*)(g_xh + (size_t)s * Hh))[sub];   // 8 halves
    uint4 pb = ((const uint4*)(g_xh + (size_t)d * Hh))[sub];
    // fp16 products (unbiased ~5e-4 rel err), fp32 accumulation
    __half2 p0 = __hmul2(*(__half2*)&pa.x, *(__half2*)&pb.x);
    __half2 p1 = __hmul2(*(__half2*)&pa.y, *(__half2*)&pb.y);
    __half2 p2 = __hmul2(*(__half2*)&pa.z, *(__half2*)&pb.z);
    __half2 p3 = __hmul2(*(__half2*)&pa.w, *(__half2*)&pb.w);
    float2 f0 = __half22float2(p0);
    float2 f1 = __half22float2(p1);
    float2 f2 = __half22float2(p2);
    float2 f3 = __half22float2(p3);
    float dot = (f0.x + f0.y) + (f1.x + f1.y) + (f2.x + f2.y) + (f3.x + f3.y);
    #pragma unroll
    for (int o = 8; o; o >>= 1) dot += __shfl_xor_sync(0xffffffffu, dot, o);
    if (sub == 0) {
        int ss_ = ld_idx(sat, (int)s, is64);
        int sd_ = ld_idx(sat, (int)d, is64);
        float f = (ss_ != sd_) ? 0.36787944117144233f : 1.0f;  // exp(-1)
        float ew = fmaxf(dot * f, 1e-4f);
        g_ew[e] = ew;
        atomicAdd(&g_deg[d], ew);
        atomicAdd(&g_cnt[d], 1);
    }
}

// ---------------- dinv = (deg + 1)^-0.5 ----------------
__global__ void k_dinv() {
    int i = blockIdx.x * blockDim.x + threadIdx.x;
    if (i < Nn) g_dinv[i] = rsqrtf(g_deg[i] + 1.0f);
}

// ------------- single-block prefix scan (counts only) ----------------------
__global__ __launch_bounds__(1024) void k_scan() {
    __shared__ int sh[1024];
    const int t = threadIdx.x;
    const int CH = (Nn + 1023) / 1024;
    int beg = t * CH;
    int end = beg + CH; if (end > Nn) end = Nn;
    int sum = 0;
    for (int i = beg; i < end; i++) sum += g_cnt[i];
    sh[t] = sum;
    __syncthreads();
    for (int off = 1; off < 1024; off <<= 1) {
        int v = 0;
        if (t >= off) v = sh[t - off];
        __syncthreads();
        if (t >= off) sh[t] += v;
        __syncthreads();
    }
    int run = (t == 0) ? 0 : sh[t - 1];
    for (int i = beg; i < end; i++) {
        g_rowptr[i] = run;
        g_cur[i]    = run;
        run += g_cnt[i];
    }
    if (t == 1023) g_rowptr[Nn] = sh[1023];
}

// ---------------- CSR fill ----------------
__global__ void k_fill(const int* __restrict__ ei) {
    int e = blockIdx.x * blockDim.x + threadIdx.x;
    if (e >= Ee) return;
    int is64 = (g_not_i64 == 0);
    unsigned s = (unsigned)ld_idx(ei, e, is64);
    unsigned d = (unsigned)ld_idx(ei, Ee + e, is64);
    if (s >= Nn || d >= Nn) return;
    float nrm = g_dinv[s] * g_ew[e] * g_dinv[d];
    int pos = atomicAdd(&g_cur[d], 1);
    g_csr_src[pos] = (int)s;
    g_csr_nrm[pos] = nrm;
}

// ------------- tensor-core GEMM: g_xt(fp32) = g_ah @ W(half) ---------------
__global__ __launch_bounds__(256) void k_gemmh(int which) {
    extern __shared__ __align__(32) __half sh[];
    __half* Ah = sh;               // [128][SK]
    __half* Wh = sh + 128 * SK;    // [128][SK]
    const __half* __restrict__ W = which ? g_W2h : g_W1h;
    int tid = threadIdx.x;
    int row0 = blockIdx.x * 128;

    for (int i = tid; i < 128 * 16; i += 256) {
        int r = i >> 4, c = i & 15;
        *((uint4*)(Wh + r * SK + c * 8)) = ((const uint4*)(W + r * 128 + c * 8))[0];
    }
    for (int i = tid; i < 128 * 16; i += 256) {
        int r = i >> 4, c = i & 15;
        int gr = row0 + r;
        uint4 v = make_uint4(0u, 0u, 0u, 0u);
        if (gr < Nn) v = ((const uint4*)(g_ah + (size_t)gr * 128 + c * 8))[0];
        *((uint4*)(Ah + r * SK + c * 8)) = v;
    }
    __syncthreads();

    int w = tid >> 5;
    wmma::fragment<wmma::accumulator, 16, 16, 16, float> acc[8];
    #pragma unroll
    for (int n = 0; n < 8; n++) wmma::fill_fragment(acc[n], 0.0f);

    #pragma unroll
    for (int k = 0; k < 8; k++) {
        wmma::fragment<wmma::matrix_a, 16, 16, 16, __half, wmma::row_major> af;
        wmma::load_matrix_sync(af, Ah + (w * 16) * SK + k * 16, SK);
        #pragma unroll
        for (int n = 0; n < 8; n++) {
            wmma::fragment<wmma::matrix_b, 16, 16, 16, __half, wmma::row_major> bf;
            wmma::load_matrix_sync(bf, Wh + (k * 16) * SK + n * 16, SK);
            wmma::mma_sync(acc[n], af, bf, acc[n]);
        }
    }

    int gr0 = row0 + w * 16;
    if (gr0 < Nn) {   // Nn multiple of 16: tile fully valid or fully out
        #pragma unroll
        for (int n = 0; n < 8; n++)
            wmma::store_matrix_sync(g_xt + (size_t)gr0 * 128 + n * 16, acc[n],
                                    128, wmma::mem_row_major);
    }
}

// ----- fused CSR aggregation (fp32, 2-way) + self-loop + bias + relu -------
// to_h1=1: write g_ah (fp16).  to_h1=0: write outext fp32 AND y head.
__global__ void k_aggc(const float* __restrict__ b, float* __restrict__ outext,
                       const float* __restrict__ Wc, const float* __restrict__ bc,
                       float* __restrict__ y, int to_h1) {
    int node = (blockIdx.x * blockDim.x + threadIdx.x) >> 5;
    int lane = threadIdx.x & 31;
    if (node >= Nn) return;
    int beg = g_rowptr[node];
    int end = g_rowptr[node + 1];

    float4 acc0 = make_float4(0.f, 0.f, 0.f, 0.f);
    float4 acc1 = make_float4(0.f, 0.f, 0.f, 0.f);

    int p = beg;
    for (; p + 1 < end; p += 2) {
        int   s0 = g_csr_src[p],     s1 = g_csr_src[p + 1];
        float n0 = g_csr_nrm[p],     n1 = g_csr_nrm[p + 1];
        float4 v0 = ((const float4*)(g_xt + (size_t)s0 * Hh))[lane];
        float4 v1 = ((const float4*)(g_xt + (size_t)s1 * Hh))[lane];
        acc0.x += v0.x * n0; acc0.y += v0.y * n0; acc0.z += v0.z * n0; acc0.w += v0.w * n0;
        acc1.x += v1.x * n1; acc1.y += v1.y * n1; acc1.z += v1.z * n1; acc1.w += v1.w * n1;
    }
    if (p < end) {
        int   s0 = g_csr_src[p];
        float n0 = g_csr_nrm[p];
        float4 v0 = ((const float4*)(g_xt + (size_t)s0 * Hh))[lane];
        acc0.x += v0.x * n0; acc0.y += v0.y * n0; acc0.z += v0.z * n0; acc0.w += v0.w * n0;
    }

    float di = g_dinv[node];
    float d2 = di * di;
    float4 self = ((const float4*)(g_xt + (size_t)node * Hh))[lane];
    float4 bb = ((const float4*)b)[lane];
    float4 r;
    r.x = fmaxf(acc0.x + acc1.x + self.x * d2 + bb.x, 0.f);
    r.y = fmaxf(acc0.y + acc1.y + self.y * d2 + bb.y, 0.f);
    r.z = fmaxf(acc0.z + acc1.z + self.z * d2 + bb.z, 0.f);
    r.w = fmaxf(acc0.w + acc1.w + self.w * d2 + bb.w, 0.f);

    if (to_h1) {
        __half2 h0 = __floats2half2_rn(r.x, r.y);
        __half2 h1 = __floats2half2_rn(r.z, r.w);
        uint2 pk; pk.x = *(unsigned*)&h0; pk.y = *(unsigned*)&h1;
        ((uint2*)(g_ah + (size_t)node * Hh))[lane] = pk;
    } else {
        ((float4*)(outext + (size_t)node * Hh))[lane] = r;
        float4 wv = ((const float4*)Wc)[lane];
        float dot = r.x * wv.x + r.y * wv.y + r.z * wv.z + r.w * wv.w;
        #pragma unroll
        for (int o = 16; o; o >>= 1) dot += __shfl_xor_sync(0xffffffffu, dot, o);
        if (lane == 0) y[node] = dot + bc[0];
    }
}

// ---------------- launch ----------------
extern "C" void kernel_launch(void* const* d_in, const int* in_sizes, int n_in,
                              void* d_out, int out_size) {
    int ix = 0, iei = 1, isa = 2, iW1 = 3, ib1 = 4, iW2 = 5, ib2 = 6, iWc = 7, ibc = 8;
    if (n_in >= 9 && in_sizes[0] != 6400000) {
        if (in_sizes[0] == 16384 && in_sizes[1] == 16384) {
            iW1 = 0; iW2 = 1; iWc = 2; ib1 = 3; ib2 = 4; ibc = 5; iei = 6; isa = 7; ix = 8;
        } else {
            int c128a = -1, c128b = -1, c128c = -1, w16a = -1, w16b = -1;
            for (int i = 0; i < n_in; i++) {
                int s = in_sizes[i];
                if (s == 6400000) ix = i;
                else if (s == 1600000 || s == 3200000) iei = i;
                else if (s == 50000 || s == 100000) isa = i;
                else if (s == 16384) { if (w16a < 0) w16a = i; else w16b = i; }
                else if (s == 128) { if (c128a < 0) c128a = i; else if (c128b < 0) c128b = i; else c128c = i; }
                else if (s == 1) ibc = i;
            }
            iW1 = w16a; iW2 = w16b; ib1 = c128a; ib2 = c128b; iWc = c128c;
        }
    }

    const float* x  = (const float*)d_in[ix];
    const int*   ei = (const int*)d_in[iei];
    const int*   sa = (const int*)d_in[isa];
    const float* W1 = (const float*)d_in[iW1];
    const float* b1 = (const float*)d_in[ib1];
    const float* W2 = (const float*)d_in[iW2];
    const float* b2 = (const float*)d_in[ib2];
    const float* Wc = (const float*)d_in[iWc];
    const float* bc = (const float*)d_in[ibc];

    float* out  = (float*)d_out;
    float* yout = out;        // [N]
    float* hout = out + Nn;   // [N, 128]

    const int T = 256;
    const int gN     = (Nn + T - 1) / T;
    const int gNwarp = (Nn + 7) / 8;
    const int gE16   = (Ee * 16 + T - 1) / T;
    const int gE     = (Ee + T - 1) / T;
    const int gGemm  = (Nn + 127) / 128;

    static int once = 0;
    if (!once) {
        cudaFuncSetAttribute(k_gemmh, cudaFuncAttributeMaxDynamicSharedMemorySize,
                             2 * 128 * SK * (int)sizeof(__half));
        once = 1;
    }
    const int SMEM = 2 * 128 * SK * (int)sizeof(__half);  // 69632 B

    k_init<<<gN, T>>>();
    k_detect<<<1, 256>>>(ei);

    k_xprep<<<gNwarp, T>>>(x);
    k_w2h<<<(2 * Hh * Hh + T - 1) / T, T>>>(W1, W2);
    k_edge<<<gE16, T>>>(ei, sa);

    k_scan<<<1, 1024>>>();
    k_dinv<<<gN, T>>>();
    k_fill<<<gE, T>>>(ei);

    // layer 1
    k_gemmh<<<gGemm, T, SMEM>>>(0);
    k_aggc<<<gNwarp, T>>>(b1, nullptr, nullptr, nullptr, nullptr, 1);

    // layer 2 (+fused head)
    k_gemmh<<<gGemm, T, SMEM>>>(1);
    k_aggc<<<gNwarp, T>>>(b2, hout, Wc, bc, yout, 0);
}

// round 15
// speedup vs baseline: 1.2112x; 1.0093x over previous
#include <cuda_runtime.h>
#include <cuda_fp16.h>
#include <mma.h>

using namespace nvcuda;

#define Nn 50000
#define Ee 800000
#define Hh 128
#define SK 136   // padded smem stride (halves)

// ---------------- scratch (device globals; NEVER passed as kernel args) ----
__device__ __half g_xh[(size_t)Nn * Hh];    // x rows normalized, fp16 (cosine)
__device__ __half g_ah[(size_t)Nn * Hh];    // GEMM A operand, fp16 (x or h1)
__device__ __half g_W1h[Hh * Hh];
__device__ __half g_W2h[Hh * Hh];
__device__ float g_ew[Ee];
__device__ float g_deg[Nn];
__device__ float g_dinv[Nn];
__device__ float g_xt[(size_t)Nn * Hh];     // GEMM output fp32 (gathered by aggc)
__device__ int   g_cnt[Nn];
__device__ int   g_rowptr[Nn + 1];
__device__ int   g_cur[Nn];
__device__ int   g_csr_src[Ee];
__device__ float g_csr_nrm[Ee];
__device__ int   g_not_i64;

__device__ __forceinline__ int ld_idx(const int* __restrict__ p, int i, int is64) {
    return is64 ? p[2 * i] : p[i];
}

// ---------------- init ----------------
__global__ void k_init() {
    int i = blockIdx.x * blockDim.x + threadIdx.x;
    if (i < Nn) { g_cnt[i] = 0; g_deg[i] = 0.f; }
    if (i == 0) g_not_i64 = 0;
}

// ---- dtype detection: sample 2048 odd words (single block, ~2us) ----------
__global__ void k_detect(const int* __restrict__ ei) {
    int nz = 0;
    for (int i = threadIdx.x; i < 2048; i += blockDim.x)
        nz |= (ei[2 * i + 1] != 0);
    #pragma unroll
    for (int o = 16; o; o >>= 1) nz |= __shfl_xor_sync(0xffffffffu, nz, o);
    if ((threadIdx.x & 31) == 0 && nz) atomicOr(&g_not_i64, 1);
}

// ------- normalize rows of x into fp16 (g_xh) AND raw fp16 copy (g_ah) -----
__global__ void k_xprep(const float* __restrict__ x) {
    int node = (blockIdx.x * blockDim.x + threadIdx.x) >> 5;
    int lane = threadIdx.x & 31;
    if (node >= Nn) return;
    float4 v = ((const float4*)(x + (size_t)node * Hh))[lane];
    float ss = v.x * v.x + v.y * v.y + v.z * v.z + v.w * v.w;
    #pragma unroll
    for (int o = 16; o; o >>= 1) ss += __shfl_xor_sync(0xffffffffu, ss, o);
    float inv = 1.0f / fmaxf(sqrtf(ss), 1e-8f);
    __half2 n0 = __floats2half2_rn(v.x * inv, v.y * inv);
    __half2 n1 = __floats2half2_rn(v.z * inv, v.w * inv);
    uint2 pn; pn.x = *(unsigned*)&n0; pn.y = *(unsigned*)&n1;
    ((uint2*)(g_xh + (size_t)node * Hh))[lane] = pn;
    __half2 r0 = __floats2half2_rn(v.x, v.y);
    __half2 r1 = __floats2half2_rn(v.z, v.w);
    uint2 pr; pr.x = *(unsigned*)&r0; pr.y = *(unsigned*)&r1;
    ((uint2*)(g_ah + (size_t)node * Hh))[lane] = pr;
}

// ---------------- convert W1, W2 to fp16 ----------------
__global__ void k_w2h(const float* __restrict__ W1, const float* __restrict__ W2) {
    int i = blockIdx.x * blockDim.x + threadIdx.x;
    if (i < Hh * Hh) g_W1h[i] = __float2half_rn(W1[i]);
    else if (i < 2 * Hh * Hh) g_W2h[i - Hh * Hh] = __float2half_rn(W2[i - Hh * Hh]);
}

// ------- edge weights + degree + histogram: 16 lanes per edge --------------
__global__ void k_edge(const int* __restrict__ ei,
                       const int* __restrict__ sat) {
    int gt = blockIdx.x * blockDim.x + threadIdx.x;
    int e = gt >> 4;                 // 2 edges per warp
    int sub = threadIdx.x & 15;
    if (e >= Ee) return;
    int is64 = (g_not_i64 == 0);
    unsigned s = (unsigned)ld_idx(ei, e, is64);
    unsigned d = (unsigned)ld_idx(ei, Ee + e, is64);
    if (s >= Nn || d >= Nn) return;   // never fault
    uint4 pa = ((const uint4*)(g_xh + (size_t)s * Hh))[sub];   // 8 halves
    uint4 pb = ((const uint4*)(g_xh + (size_t)d * Hh))[sub];
    __half2 p0 = __hmul2(*(__half2*)&pa.x, *(__half2*)&pb.x);
    __half2 p1 = __hmul2(*(__half2*)&pa.y, *(__half2*)&pb.y);
    __half2 p2 = __hmul2(*(__half2*)&pa.z, *(__half2*)&pb.z);
    __half2 p3 = __hmul2(*(__half2*)&pa.w, *(__half2*)&pb.w);
    float2 f0 = __half22float2(p0);
    float2 f1 = __half22float2(p1);
    float2 f2 = __half22float2(p2);
    float2 f3 = __half22float2(p3);
    float dot = (f0.x + f0.y) + (f1.x + f1.y) + (f2.x + f2.y) + (f3.x + f3.y);
    #pragma unroll
    for (int o = 8; o; o >>= 1) dot += __shfl_xor_sync(0xffffffffu, dot, o);
    if (sub == 0) {
        int ss_ = ld_idx(sat, (int)s, is64);
        int sd_ = ld_idx(sat, (int)d, is64);
        float f = (ss_ != sd_) ? 0.36787944117144233f : 1.0f;  // exp(-1)
        float ew = fmaxf(dot * f, 1e-4f);
        g_ew[e] = ew;
        atomicAdd(&g_deg[d], ew);
        atomicAdd(&g_cnt[d], 1);
    }
}

// ---------------- dinv = (deg + 1)^-0.5 ----------------
__global__ void k_dinv() {
    int i = blockIdx.x * blockDim.x + threadIdx.x;
    if (i < Nn) g_dinv[i] = rsqrtf(g_deg[i] + 1.0f);
}

// ------------- single-block prefix scan (counts only) ----------------------
__global__ __launch_bounds__(1024) void k_scan() {
    __shared__ int sh[1024];
    const int t = threadIdx.x;
    const int CH = (Nn + 1023) / 1024;
    int beg = t * CH;
    int end = beg + CH; if (end > Nn) end = Nn;
    int sum = 0;
    for (int i = beg; i < end; i++) sum += g_cnt[i];
    sh[t] = sum;
    __syncthreads();
    for (int off = 1; off < 1024; off <<= 1) {
        int v = 0;
        if (t >= off) v = sh[t - off];
        __syncthreads();
        if (t >= off) sh[t] += v;
        __syncthreads();
    }
    int run = (t == 0) ? 0 : sh[t - 1];
    for (int i = beg; i < end; i++) {
        g_rowptr[i] = run;
        g_cur[i]    = run;
        run += g_cnt[i];
    }
    if (t == 1023) g_rowptr[Nn] = sh[1023];
}

// ---------------- CSR fill ----------------
__global__ void k_fill(const int* __restrict__ ei) {
    int e = blockIdx.x * blockDim.x + threadIdx.x;
    if (e >= Ee) return;
    int is64 = (g_not_i64 == 0);
    unsigned s = (unsigned)ld_idx(ei, e, is64);
    unsigned d = (unsigned)ld_idx(ei, Ee + e, is64);
    if (s >= Nn || d >= Nn) return;
    float nrm = g_dinv[s] * g_ew[e] * g_dinv[d];
    int pos = atomicAdd(&g_cur[d], 1);
    g_csr_src[pos] = (int)s;
    g_csr_nrm[pos] = nrm;
}

// ------------- tensor-core GEMM: g_xt(fp32) = g_ah @ W(half) ---------------
__global__ __launch_bounds__(256) void k_gemmh(int which) {
    extern __shared__ __align__(32) __half sh[];
    __half* Ah = sh;               // [128][SK]
    __half* Wh = sh + 128 * SK;    // [128][SK]
    const __half* __restrict__ W = which ? g_W2h : g_W1h;
    int tid = threadIdx.x;
    int row0 = blockIdx.x * 128;

    for (int i = tid; i < 128 * 16; i += 256) {
        int r = i >> 4, c = i & 15;
        *((uint4*)(Wh + r * SK + c * 8)) = ((const uint4*)(W + r * 128 + c * 8))[0];
    }
    for (int i = tid; i < 128 * 16; i += 256) {
        int r = i >> 4, c = i & 15;
        int gr = row0 + r;
        uint4 v = make_uint4(0u, 0u, 0u, 0u);
        if (gr < Nn) v = ((const uint4*)(g_ah + (size_t)gr * 128 + c * 8))[0];
        *((uint4*)(Ah + r * SK + c * 8)) = v;
    }
    __syncthreads();

    int w = tid >> 5;
    wmma::fragment<wmma::accumulator, 16, 16, 16, float> acc[8];
    #pragma unroll
    for (int n = 0; n < 8; n++) wmma::fill_fragment(acc[n], 0.0f);

    #pragma unroll
    for (int k = 0; k < 8; k++) {
        wmma::fragment<wmma::matrix_a, 16, 16, 16, __half, wmma::row_major> af;
        wmma::load_matrix_sync(af, Ah + (w * 16) * SK + k * 16, SK);
        #pragma unroll
        for (int n = 0; n < 8; n++) {
            wmma::fragment<wmma::matrix_b, 16, 16, 16, __half, wmma::row_major> bf;
            wmma::load_matrix_sync(bf, Wh + (k * 16) * SK + n * 16, SK);
            wmma::mma_sync(acc[n], af, bf, acc[n]);
        }
    }

    int gr0 = row0 + w * 16;
    if (gr0 < Nn) {   // Nn multiple of 16: tile fully valid or fully out
        #pragma unroll
        for (int n = 0; n < 8; n++)
            wmma::store_matrix_sync(g_xt + (size_t)gr0 * 128 + n * 16, acc[n],
                                    128, wmma::mem_row_major);
    }
}

// ----- fused CSR aggregation (fp32, 4-way MLP) + self-loop + bias + relu ---
// to_h1=1: write g_ah (fp16).  to_h1=0: write outext fp32 AND y head.
__global__ void k_aggc(const float* __restrict__ b, float* __restrict__ outext,
                       const float* __restrict__ Wc, const float* __restrict__ bc,
                       float* __restrict__ y, int to_h1) {
    int node = (blockIdx.x * blockDim.x + threadIdx.x) >> 5;
    int lane = threadIdx.x & 31;
    if (node >= Nn) return;
    int beg = g_rowptr[node];
    int end = g_rowptr[node + 1];

    float4 acc0 = make_float4(0.f, 0.f, 0.f, 0.f);
    float4 acc1 = make_float4(0.f, 0.f, 0.f, 0.f);

    int p = beg;
    for (; p + 3 < end; p += 4) {
        int   s0 = g_csr_src[p],     s1 = g_csr_src[p + 1];
        int   s2 = g_csr_src[p + 2], s3 = g_csr_src[p + 3];
        float n0 = g_csr_nrm[p],     n1 = g_csr_nrm[p + 1];
        float n2 = g_csr_nrm[p + 2], n3 = g_csr_nrm[p + 3];
        float4 v0 = ((const float4*)(g_xt + (size_t)s0 * Hh))[lane];
        float4 v1 = ((const float4*)(g_xt + (size_t)s1 * Hh))[lane];
        float4 v2 = ((const float4*)(g_xt + (size_t)s2 * Hh))[lane];
        float4 v3 = ((const float4*)(g_xt + (size_t)s3 * Hh))[lane];
        acc0.x += v0.x * n0; acc0.y += v0.y * n0; acc0.z += v0.z * n0; acc0.w += v0.w * n0;
        acc1.x += v1.x * n1; acc1.y += v1.y * n1; acc1.z += v1.z * n1; acc1.w += v1.w * n1;
        acc0.x += v2.x * n2; acc0.y += v2.y * n2; acc0.z += v2.z * n2; acc0.w += v2.w * n2;
        acc1.x += v3.x * n3; acc1.y += v3.y * n3; acc1.z += v3.z * n3; acc1.w += v3.w * n3;
    }
    for (; p < end; p++) {
        int   s0 = g_csr_src[p];
        float n0 = g_csr_nrm[p];
        float4 v0 = ((const float4*)(g_xt + (size_t)s0 * Hh))[lane];
        acc0.x += v0.x * n0; acc0.y += v0.y * n0; acc0.z += v0.z * n0; acc0.w += v0.w * n0;
    }

    float di = g_dinv[node];
    float d2 = di * di;
    float4 self = ((const float4*)(g_xt + (size_t)node * Hh))[lane];
    float4 bb = ((const float4*)b)[lane];
    float4 r;
    r.x = fmaxf(acc0.x + acc1.x + self.x * d2 + bb.x, 0.f);
    r.y = fmaxf(acc0.y + acc1.y + self.y * d2 + bb.y, 0.f);
    r.z = fmaxf(acc0.z + acc1.z + self.z * d2 + bb.z, 0.f);
    r.w = fmaxf(acc0.w + acc1.w + self.w * d2 + bb.w, 0.f);

    if (to_h1) {
        __half2 h0 = __floats2half2_rn(r.x, r.y);
        __half2 h1 = __floats2half2_rn(r.z, r.w);
        uint2 pk; pk.x = *(unsigned*)&h0; pk.y = *(unsigned*)&h1;
        ((uint2*)(g_ah + (size_t)node * Hh))[lane] = pk;
    } else {
        ((float4*)(outext + (size_t)node * Hh))[lane] = r;
        float4 wv = ((const float4*)Wc)[lane];
        float dot = r.x * wv.x + r.y * wv.y + r.z * wv.z + r.w * wv.w;
        #pragma unroll
        for (int o = 16; o; o >>= 1) dot += __shfl_xor_sync(0xffffffffu, dot, o);
        if (lane == 0) y[node] = dot + bc[0];
    }
}

// ---------------- launch ----------------
extern "C" void kernel_launch(void* const* d_in, const int* in_sizes, int n_in,
                              void* d_out, int out_size) {
    int ix = 0, iei = 1, isa = 2, iW1 = 3, ib1 = 4, iW2 = 5, ib2 = 6, iWc = 7, ibc = 8;
    if (n_in >= 9 && in_sizes[0] != 6400000) {
        if (in_sizes[0] == 16384 && in_sizes[1] == 16384) {
            iW1 = 0; iW2 = 1; iWc = 2; ib1 = 3; ib2 = 4; ibc = 5; iei = 6; isa = 7; ix = 8;
        } else {
            int c128a = -1, c128b = -1, c128c = -1, w16a = -1, w16b = -1;
            for (int i = 0; i < n_in; i++) {
                int s = in_sizes[i];
                if (s == 6400000) ix = i;
                else if (s == 1600000 || s == 3200000) iei = i;
                else if (s == 50000 || s == 100000) isa = i;
                else if (s == 16384) { if (w16a < 0) w16a = i; else w16b = i; }
                else if (s == 128) { if (c128a < 0) c128a = i; else if (c128b < 0) c128b = i; else c128c = i; }
                else if (s == 1) ibc = i;
            }
            iW1 = w16a; iW2 = w16b; ib1 = c128a; ib2 = c128b; iWc = c128c;
        }
    }

    const float* x  = (const float*)d_in[ix];
    const int*   ei = (const int*)d_in[iei];
    const int*   sa = (const int*)d_in[isa];
    const float* W1 = (const float*)d_in[iW1];
    const float* b1 = (const float*)d_in[ib1];
    const float* W2 = (const float*)d_in[iW2];
    const float* b2 = (const float*)d_in[ib2];
    const float* Wc = (const float*)d_in[iWc];
    const float* bc = (const float*)d_in[ibc];

    float* out  = (float*)d_out;
    float* yout = out;        // [N]
    float* hout = out + Nn;   // [N, 128]

    const int T = 256;
    const int gN     = (Nn + T - 1) / T;
    const int gNwarp = (Nn + 7) / 8;
    const int gE16   = (Ee * 16 + T - 1) / T;
    const int gE     = (Ee + T - 1) / T;
    const int gGemm  = (Nn + 127) / 128;

    static int once = 0;
    if (!once) {
        cudaFuncSetAttribute(k_gemmh, cudaFuncAttributeMaxDynamicSharedMemorySize,
                             2 * 128 * SK * (int)sizeof(__half));
        once = 1;
    }
    const int SMEM = 2 * 128 * SK * (int)sizeof(__half);  // 69632 B

    k_init<<<gN, T>>>();
    k_detect<<<1, 256>>>(ei);

    k_xprep<<<gNwarp, T>>>(x);
    k_w2h<<<(2 * Hh * Hh + T - 1) / T, T>>>(W1, W2);
    k_edge<<<gE16, T>>>(ei, sa);

    k_scan<<<1, 1024>>>();
    k_dinv<<<gN, T>>>();
    k_fill<<<gE, T>>>(ei);

    // layer 1
    k_gemmh<<<gGemm, T, SMEM>>>(0);
    k_aggc<<<gNwarp, T>>>(b1, nullptr, nullptr, nullptr, nullptr, 1);

    // layer 2 (+fused head)
    k_gemmh<<<gGemm, T, SMEM>>>(1);
    k_aggc<<<gNwarp, T>>>(b2, hout, Wc, bc, yout, 0);
}

// round 16
// speedup vs baseline: 1.3366x; 1.1036x over previous
#include <cuda_runtime.h>
#include <cuda_fp16.h>
#include <mma.h>

using namespace nvcuda;

#define Nn 50000
#define Ee 800000
#define Hh 128
#define SK 136   // padded smem stride (halves)

// ---------------- scratch (device globals; NEVER passed as kernel args) ----
__device__ __half g_xh[(size_t)Nn * Hh];    // x rows normalized, fp16 (cosine)
__device__ __half g_ah[(size_t)Nn * Hh];    // GEMM A operand, fp16 (x or h1)
__device__ __half g_W1h[Hh * Hh];
__device__ __half g_W2h[Hh * Hh];
__device__ float g_ew[Ee];
__device__ float g_deg[Nn];
__device__ float g_dinv[Nn];
__device__ float g_xt[(size_t)Nn * Hh];     // GEMM output fp32 (gathered by aggc)
__device__ int   g_cnt[Nn];
__device__ int   g_rowptr[Nn + 1];
__device__ int   g_cur[Nn];
__device__ int   g_csr_src[Ee];
__device__ float g_csr_nrm[Ee];
__device__ int   g_not_i64;

__device__ __forceinline__ int ld_idx(const int* __restrict__ p, int i, int is64) {
    return is64 ? p[2 * i] : p[i];
}

// ---------------- init ----------------
__global__ void k_init() {
    int i = blockIdx.x * blockDim.x + threadIdx.x;
    if (i < Nn) { g_cnt[i] = 0; g_deg[i] = 0.f; }
    if (i == 0) g_not_i64 = 0;
}

// ---- dtype detection: sample 2048 odd words (single block, ~2us) ----------
__global__ void k_detect(const int* __restrict__ ei) {
    int nz = 0;
    for (int i = threadIdx.x; i < 2048; i += blockDim.x)
        nz |= (ei[2 * i + 1] != 0);
    #pragma unroll
    for (int o = 16; o; o >>= 1) nz |= __shfl_xor_sync(0xffffffffu, nz, o);
    if ((threadIdx.x & 31) == 0 && nz) atomicOr(&g_not_i64, 1);
}

// ------- normalize rows of x into fp16 (g_xh) AND raw fp16 copy (g_ah) -----
__global__ void k_xprep(const float* __restrict__ x) {
    int node = (blockIdx.x * blockDim.x + threadIdx.x) >> 5;
    int lane = threadIdx.x & 31;
    if (node >= Nn) return;
    float4 v = ((const float4*)(x + (size_t)node * Hh))[lane];
    float ss = v.x * v.x + v.y * v.y + v.z * v.z + v.w * v.w;
    #pragma unroll
    for (int o = 16; o; o >>= 1) ss += __shfl_xor_sync(0xffffffffu, ss, o);
    float inv = 1.0f / fmaxf(sqrtf(ss), 1e-8f);
    __half2 n0 = __floats2half2_rn(v.x * inv, v.y * inv);
    __half2 n1 = __floats2half2_rn(v.z * inv, v.w * inv);
    uint2 pn; pn.x = *(unsigned*)&n0; pn.y = *(unsigned*)&n1;
    ((uint2*)(g_xh + (size_t)node * Hh))[lane] = pn;
    __half2 r0 = __floats2half2_rn(v.x, v.y);
    __half2 r1 = __floats2half2_rn(v.z, v.w);
    uint2 pr; pr.x = *(unsigned*)&r0; pr.y = *(unsigned*)&r1;
    ((uint2*)(g_ah + (size_t)node * Hh))[lane] = pr;
}

// ---------------- convert W1, W2 to fp16 ----------------
__global__ void k_w2h(const float* __restrict__ W1, const float* __restrict__ W2) {
    int i = blockIdx.x * blockDim.x + threadIdx.x;
    if (i < Hh * Hh) g_W1h[i] = __float2half_rn(W1[i]);
    else if (i < 2 * Hh * Hh) g_W2h[i - Hh * Hh] = __float2half_rn(W2[i - Hh * Hh]);
}

// ------- edge weights + degree + histogram: 8 lanes per edge ---------------
// 4 edges per warp, each lane loads 2x uint4 per row -> 8 independent
// 128B requests in flight per warp (2x the 16-lane variant's MLP).
__global__ void k_edge(const int* __restrict__ ei,
                       const int* __restrict__ sat) {
    int gt = blockIdx.x * blockDim.x + threadIdx.x;
    int e = gt >> 3;                 // 4 edges per warp
    int sub = threadIdx.x & 7;
    if (e >= Ee) return;
    int is64 = (g_not_i64 == 0);
    unsigned s = (unsigned)ld_idx(ei, e, is64);
    unsigned d = (unsigned)ld_idx(ei, Ee + e, is64);
    if (s >= Nn || d >= Nn) return;   // never fault
    const uint4* ra = (const uint4*)(g_xh + (size_t)s * Hh);
    const uint4* rb = (const uint4*)(g_xh + (size_t)d * Hh);
    uint4 pa0 = ra[sub];
    uint4 pb0 = rb[sub];
    uint4 pa1 = ra[sub + 8];
    uint4 pb1 = rb[sub + 8];
    // fp16 products, fp32 accumulation
    __half2 q0 = __hmul2(*(__half2*)&pa0.x, *(__half2*)&pb0.x);
    __half2 q1 = __hmul2(*(__half2*)&pa0.y, *(__half2*)&pb0.y);
    __half2 q2 = __hmul2(*(__half2*)&pa0.z, *(__half2*)&pb0.z);
    __half2 q3 = __hmul2(*(__half2*)&pa0.w, *(__half2*)&pb0.w);
    __half2 q4 = __hmul2(*(__half2*)&pa1.x, *(__half2*)&pb1.x);
    __half2 q5 = __hmul2(*(__half2*)&pa1.y, *(__half2*)&pb1.y);
    __half2 q6 = __hmul2(*(__half2*)&pa1.z, *(__half2*)&pb1.z);
    __half2 q7 = __hmul2(*(__half2*)&pa1.w, *(__half2*)&pb1.w);
    float2 f0 = __half22float2(q0), f1 = __half22float2(q1);
    float2 f2 = __half22float2(q2), f3 = __half22float2(q3);
    float2 f4 = __half22float2(q4), f5 = __half22float2(q5);
    float2 f6 = __half22float2(q6), f7 = __half22float2(q7);
    float dot = ((f0.x + f0.y) + (f1.x + f1.y)) + ((f2.x + f2.y) + (f3.x + f3.y))
              + ((f4.x + f4.y) + (f5.x + f5.y)) + ((f6.x + f6.y) + (f7.x + f7.y));
    #pragma unroll
    for (int o = 4; o; o >>= 1) dot += __shfl_xor_sync(0xffffffffu, dot, o);
    if (sub == 0) {
        int ss_ = ld_idx(sat, (int)s, is64);
        int sd_ = ld_idx(sat, (int)d, is64);
        float f = (ss_ != sd_) ? 0.36787944117144233f : 1.0f;  // exp(-1)
        float ew = fmaxf(dot * f, 1e-4f);
        g_ew[e] = ew;
        atomicAdd(&g_deg[d], ew);
        atomicAdd(&g_cnt[d], 1);
    }
}

// ---------------- dinv = (deg + 1)^-0.5 ----------------
__global__ void k_dinv() {
    int i = blockIdx.x * blockDim.x + threadIdx.x;
    if (i < Nn) g_dinv[i] = rsqrtf(g_deg[i] + 1.0f);
}

// ------------- single-block prefix scan (counts only) ----------------------
__global__ __launch_bounds__(1024) void k_scan() {
    __shared__ int sh[1024];
    const int t = threadIdx.x;
    const int CH = (Nn + 1023) / 1024;
    int beg = t * CH;
    int end = beg + CH; if (end > Nn) end = Nn;
    int sum = 0;
    for (int i = beg; i < end; i++) sum += g_cnt[i];
    sh[t] = sum;
    __syncthreads();
    for (int off = 1; off < 1024; off <<= 1) {
        int v = 0;
        if (t >= off) v = sh[t - off];
        __syncthreads();
        if (t >= off) sh[t] += v;
        __syncthreads();
    }
    int run = (t == 0) ? 0 : sh[t - 1];
    for (int i = beg; i < end; i++) {
        g_rowptr[i] = run;
        g_cur[i]    = run;
        run += g_cnt[i];
    }
    if (t == 1023) g_rowptr[Nn] = sh[1023];
}

// ---------------- CSR fill ----------------
__global__ void k_fill(const int* __restrict__ ei) {
    int e = blockIdx.x * blockDim.x + threadIdx.x;
    if (e >= Ee) return;
    int is64 = (g_not_i64 == 0);
    unsigned s = (unsigned)ld_idx(ei, e, is64);
    unsigned d = (unsigned)ld_idx(ei, Ee + e, is64);
    if (s >= Nn || d >= Nn) return;
    float nrm = g_dinv[s] * g_ew[e] * g_dinv[d];
    int pos = atomicAdd(&g_cur[d], 1);
    g_csr_src[pos] = (int)s;
    g_csr_nrm[pos] = nrm;
}

// ------------- tensor-core GEMM: g_xt(fp32) = g_ah @ W(half) ---------------
__global__ __launch_bounds__(256) void k_gemmh(int which) {
    extern __shared__ __align__(32) __half sh[];
    __half* Ah = sh;               // [128][SK]
    __half* Wh = sh + 128 * SK;    // [128][SK]
    const __half* __restrict__ W = which ? g_W2h : g_W1h;
    int tid = threadIdx.x;
    int row0 = blockIdx.x * 128;

    for (int i = tid; i < 128 * 16; i += 256) {
        int r = i >> 4, c = i & 15;
        *((uint4*)(Wh + r * SK + c * 8)) = ((const uint4*)(W + r * 128 + c * 8))[0];
    }
    for (int i = tid; i < 128 * 16; i += 256) {
        int r = i >> 4, c = i & 15;
        int gr = row0 + r;
        uint4 v = make_uint4(0u, 0u, 0u, 0u);
        if (gr < Nn) v = ((const uint4*)(g_ah + (size_t)gr * 128 + c * 8))[0];
        *((uint4*)(Ah + r * SK + c * 8)) = v;
    }
    __syncthreads();

    int w = tid >> 5;
    wmma::fragment<wmma::accumulator, 16, 16, 16, float> acc[8];
    #pragma unroll
    for (int n = 0; n < 8; n++) wmma::fill_fragment(acc[n], 0.0f);

    #pragma unroll
    for (int k = 0; k < 8; k++) {
        wmma::fragment<wmma::matrix_a, 16, 16, 16, __half, wmma::row_major> af;
        wmma::load_matrix_sync(af, Ah + (w * 16) * SK + k * 16, SK);
        #pragma unroll
        for (int n = 0; n < 8; n++) {
            wmma::fragment<wmma::matrix_b, 16, 16, 16, __half, wmma::row_major> bf;
            wmma::load_matrix_sync(bf, Wh + (k * 16) * SK + n * 16, SK);
            wmma::mma_sync(acc[n], af, bf, acc[n]);
        }
    }

    int gr0 = row0 + w * 16;
    if (gr0 < Nn) {   // Nn multiple of 16: tile fully valid or fully out
        #pragma unroll
        for (int n = 0; n < 8; n++)
            wmma::store_matrix_sync(g_xt + (size_t)gr0 * 128 + n * 16, acc[n],
                                    128, wmma::mem_row_major);
    }
}

// ----- fused CSR aggregation (fp32, 4-way MLP) + self-loop + bias + relu ---
// to_h1=1: write g_ah (fp16).  to_h1=0: write outext fp32 AND y head.
__global__ void k_aggc(const float* __restrict__ b, float* __restrict__ outext,
                       const float* __restrict__ Wc, const float* __restrict__ bc,
                       float* __restrict__ y, int to_h1) {
    int node = (blockIdx.x * blockDim.x + threadIdx.x) >> 5;
    int lane = threadIdx.x & 31;
    if (node >= Nn) return;
    int beg = g_rowptr[node];
    int end = g_rowptr[node + 1];

    float4 acc0 = make_float4(0.f, 0.f, 0.f, 0.f);
    float4 acc1 = make_float4(0.f, 0.f, 0.f, 0.f);

    int p = beg;
    for (; p + 3 < end; p += 4) {
        int   s0 = g_csr_src[p],     s1 = g_csr_src[p + 1];
        int   s2 = g_csr_src[p + 2], s3 = g_csr_src[p + 3];
        float n0 = g_csr_nrm[p],     n1 = g_csr_nrm[p + 1];
        float n2 = g_csr_nrm[p + 2], n3 = g_csr_nrm[p + 3];
        float4 v0 = ((const float4*)(g_xt + (size_t)s0 * Hh))[lane];
        float4 v1 = ((const float4*)(g_xt + (size_t)s1 * Hh))[lane];
        float4 v2 = ((const float4*)(g_xt + (size_t)s2 * Hh))[lane];
        float4 v3 = ((const float4*)(g_xt + (size_t)s3 * Hh))[lane];
        acc0.x += v0.x * n0; acc0.y += v0.y * n0; acc0.z += v0.z * n0; acc0.w += v0.w * n0;
        acc1.x += v1.x * n1; acc1.y += v1.y * n1; acc1.z += v1.z * n1; acc1.w += v1.w * n1;
        acc0.x += v2.x * n2; acc0.y += v2.y * n2; acc0.z += v2.z * n2; acc0.w += v2.w * n2;
        acc1.x += v3.x * n3; acc1.y += v3.y * n3; acc1.z += v3.z * n3; acc1.w += v3.w * n3;
    }
    for (; p < end; p++) {
        int   s0 = g_csr_src[p];
        float n0 = g_csr_nrm[p];
        float4 v0 = ((const float4*)(g_xt + (size_t)s0 * Hh))[lane];
        acc0.x += v0.x * n0; acc0.y += v0.y * n0; acc0.z += v0.z * n0; acc0.w += v0.w * n0;
    }

    float di = g_dinv[node];
    float d2 = di * di;
    float4 self = ((const float4*)(g_xt + (size_t)node * Hh))[lane];
    float4 bb = ((const float4*)b)[lane];
    float4 r;
    r.x = fmaxf(acc0.x + acc1.x + self.x * d2 + bb.x, 0.f);
    r.y = fmaxf(acc0.y + acc1.y + self.y * d2 + bb.y, 0.f);
    r.z = fmaxf(acc0.z + acc1.z + self.z * d2 + bb.z, 0.f);
    r.w = fmaxf(acc0.w + acc1.w + self.w * d2 + bb.w, 0.f);

    if (to_h1) {
        __half2 h0 = __floats2half2_rn(r.x, r.y);
        __half2 h1 = __floats2half2_rn(r.z, r.w);
        uint2 pk; pk.x = *(unsigned*)&h0; pk.y = *(unsigned*)&h1;
        ((uint2*)(g_ah + (size_t)node * Hh))[lane] = pk;
    } else {
        ((float4*)(outext + (size_t)node * Hh))[lane] = r;
        float4 wv = ((const float4*)Wc)[lane];
        float dot = r.x * wv.x + r.y * wv.y + r.z * wv.z + r.w * wv.w;
        #pragma unroll
        for (int o = 16; o; o >>= 1) dot += __shfl_xor_sync(0xffffffffu, dot, o);
        if (lane == 0) y[node] = dot + bc[0];
    }
}

// ---------------- launch ----------------
extern "C" void kernel_launch(void* const* d_in, const int* in_sizes, int n_in,
                              void* d_out, int out_size) {
    int ix = 0, iei = 1, isa = 2, iW1 = 3, ib1 = 4, iW2 = 5, ib2 = 6, iWc = 7, ibc = 8;
    if (n_in >= 9 && in_sizes[0] != 6400000) {
        if (in_sizes[0] == 16384 && in_sizes[1] == 16384) {
            iW1 = 0; iW2 = 1; iWc = 2; ib1 = 3; ib2 = 4; ibc = 5; iei = 6; isa = 7; ix = 8;
        } else {
            int c128a = -1, c128b = -1, c128c = -1, w16a = -1, w16b = -1;
            for (int i = 0; i < n_in; i++) {
                int s = in_sizes[i];
                if (s == 6400000) ix = i;
                else if (s == 1600000 || s == 3200000) iei = i;
                else if (s == 50000 || s == 100000) isa = i;
                else if (s == 16384) { if (w16a < 0) w16a = i; else w16b = i; }
                else if (s == 128) { if (c128a < 0) c128a = i; else if (c128b < 0) c128b = i; else c128c = i; }
                else if (s == 1) ibc = i;
            }
            iW1 = w16a; iW2 = w16b; ib1 = c128a; ib2 = c128b; iWc = c128c;
        }
    }

    const float* x  = (const float*)d_in[ix];
    const int*   ei = (const int*)d_in[iei];
    const int*   sa = (const int*)d_in[isa];
    const float* W1 = (const float*)d_in[iW1];
    const float* b1 = (const float*)d_in[ib1];
    const float* W2 = (const float*)d_in[iW2];
    const float* b2 = (const float*)d_in[ib2];
    const float* Wc = (const float*)d_in[iWc];
    const float* bc = (const float*)d_in[ibc];

    float* out  = (float*)d_out;
    float* yout = out;        // [N]
    float* hout = out + Nn;   // [N, 128]

    const int T = 256;
    const int gN     = (Nn + T - 1) / T;
    const int gNwarp = (Nn + 7) / 8;
    const int gE8    = (Ee * 8 + T - 1) / T;      // 8 lanes per edge
    const int gE     = (Ee + T - 1) / T;
    const int gGemm  = (Nn + 127) / 128;

    static int once = 0;
    if (!once) {
        cudaFuncSetAttribute(k_gemmh, cudaFuncAttributeMaxDynamicSharedMemorySize,
                             2 * 128 * SK * (int)sizeof(__half));
        once = 1;
    }
    const int SMEM = 2 * 128 * SK * (int)sizeof(__half);  // 69632 B

    k_init<<<gN, T>>>();
    k_detect<<<1, 256>>>(ei);

    k_xprep<<<gNwarp, T>>>(x);
    k_w2h<<<(2 * Hh * Hh + T - 1) / T, T>>>(W1, W2);
    k_edge<<<gE8, T>>>(ei, sa);

    k_scan<<<1, 1024>>>();
    k_dinv<<<gN, T>>>();
    k_fill<<<gE, T>>>(ei);

    // layer 1
    k_gemmh<<<gGemm, T, SMEM>>>(0);
    k_aggc<<<gNwarp, T>>>(b1, nullptr, nullptr, nullptr, nullptr, 1);

    // layer 2 (+fused head)
    k_gemmh<<<gGemm, T, SMEM>>>(1);
    k_aggc<<<gNwarp, T>>>(b2, hout, Wc, bc, yout, 0);
}